// round 9
// baseline (speedup 1.0000x reference)
#include <cuda_runtime.h>
#include <math.h>
#include <stdint.h>

#define B_     4096
#define D_     512
#define H_     512
#define V_     128
#define MAXLEN 100
#define TH3    1536   // 3*H

// ------------------------- persistent device scratch -------------------------
__device__ float g_h0[2][B_ * H_];
__device__ float g_h1[2][B_ * H_];
__device__ float g_zc0p[B_ * TH3];        // z @ Wih0[:,H:]^T + bih0 (gate-interleaved)
__device__ float g_T0p[V_ * TH3];         // emb @ Wih0[:,:H]^T (gate-interleaved)
__device__ float g_Whh0p[TH3 * H_];       // permuted: row j*3+g = Whh0[g*H+j]
__device__ float g_Wih1p[TH3 * H_];
__device__ float g_Whh1p[TH3 * H_];
__device__ float g_Wih0ep[TH3 * H_];
__device__ float g_Wih0zp[TH3 * H_];
__device__ float g_bhh0p[TH3];
__device__ float g_bi1p[TH3];
__device__ float g_bh1p[TH3];
__device__ float g_bih0p[TH3];
__device__ float g_outWt[H_ * V_];
__device__ float g_gi[B_ * TH3];          // layer1 input-GEMM scratch (position-indexed)
__device__ float g_gh[B_ * TH3];          // layer1 hidden-GEMM scratch (position-indexed)
__device__ int   g_w[B_];
__device__ int   g_eos[B_];
__device__ int   g_active[B_];            // compacted list of live rows
__device__ int   g_nact;                  // live count

// --------- accurate, fast-math-immune exp / sigmoid / tanh (identical to R3 pass) ---------
__device__ __forceinline__ float exp_acc(float x) {
    x = fminf(fmaxf(x, -87.0f), 88.0f);
    float k = rintf(x * 1.4426950408889634f);
    float f = fmaf(k, -0.693359375f, x);
    f = fmaf(k, 2.12194440e-4f, f);
    float z = f * f;
    float p = 1.9875691500e-4f;
    p = fmaf(p, f, 1.3981999507e-3f);
    p = fmaf(p, f, 8.3334519073e-3f);
    p = fmaf(p, f, 4.1665795894e-2f);
    p = fmaf(p, f, 1.6666665459e-1f);
    p = fmaf(p, f, 5.0000001201e-1f);
    float y = fmaf(p, z, f) + 1.0f;
    return __int_as_float(__float_as_int(y) + (((int)k) << 23));
}
__device__ __forceinline__ float sigmoidf_(float x) { return 1.0f / (1.0f + exp_acc(-x)); }
__device__ __forceinline__ float tanhf_(float x) {
    float e = exp_acc(2.0f * x);
    return (e - 1.0f) / (e + 1.0f);
}

// ------------------------- init: weight permutation -------------------------
__global__ void permute_kernel(const float* __restrict__ Wih0,
                               const float* __restrict__ Whh0,
                               const float* __restrict__ Wih1,
                               const float* __restrict__ Whh1,
                               const float* __restrict__ bih0,
                               const float* __restrict__ bhh0,
                               const float* __restrict__ bih1,
                               const float* __restrict__ bhh1,
                               const float* __restrict__ outW) {
    int idx = blockIdx.x * blockDim.x + threadIdx.x;
    if (idx < TH3 * H_) {
        int c = idx / H_;
        int k = idx - c * H_;
        int j = c / 3, g = c - 3 * (c / 3);
        int src = g * H_ + j;
        g_Whh0p[idx]  = Whh0[src * H_ + k];
        g_Wih1p[idx]  = Wih1[src * H_ + k];
        g_Whh1p[idx]  = Whh1[src * H_ + k];
        g_Wih0ep[idx] = Wih0[src * (H_ + D_) + k];
        g_Wih0zp[idx] = Wih0[src * (H_ + D_) + H_ + k];
        if (k == 0) {
            g_bhh0p[c] = bhh0[src];
            g_bi1p[c]  = bih1[src];
            g_bh1p[c]  = bhh1[src];
            g_bih0p[c] = bih0[src];
        }
    }
    if (idx < H_ * V_) {
        int k = idx / V_, v = idx - k * V_;
        g_outWt[idx] = outW[v * H_ + k];
    }
}

__global__ void init_state_kernel(float* __restrict__ xout, float* __restrict__ endp) {
    int b = blockIdx.x * blockDim.x + threadIdx.x;
    if (b < B_) {
        g_w[b]      = 1;
        g_eos[b]    = 0;
        g_active[b] = b;
        if (endp) endp[b] = (float)MAXLEN;
        xout[b * MAXLEN] = 1.0f;
        if (b == 0) g_nact = B_;
    }
}

// ------------------------- compaction: stable scan of live rows -------------------------
__global__ void __launch_bounds__(1024) compact_k() {
    __shared__ int cnt[1024];
    int t = threadIdx.x;
    int base = t * 4;
    int fl[4];
    int c = 0;
#pragma unroll
    for (int i = 0; i < 4; i++) { fl[i] = !g_eos[base + i]; c += fl[i]; }
    cnt[t] = c;
    __syncthreads();
    for (int off = 1; off < 1024; off <<= 1) {
        int v = (t >= off) ? cnt[t - off] : 0;
        __syncthreads();
        cnt[t] += v;
        __syncthreads();
    }
    int pos = cnt[t] - c;       // exclusive prefix
#pragma unroll
    for (int i = 0; i < 4; i++) if (fl[i]) g_active[pos++] = base + i;
    if (t == 1023) g_nact = cnt[t];
}

// ------------------------- init GEMMs (fp32 FFMA, one-time; identical to R3) -------------------------
__global__ void __launch_bounds__(256) gemm_init_kernel(const float* __restrict__ A,
                                                        const float* __restrict__ Wext,
                                                        const float* __restrict__ biasext,
                                                        int mode) {
    const float* W;
    const float* bias;
    float* C;
    float* C2 = nullptr;
    int N;
    if (mode == 0)      { W = Wext;      bias = biasext;  C = g_h0[0]; C2 = g_h1[0]; N = H_;  }
    else if (mode == 1) { W = g_Wih0zp;  bias = g_bih0p;  C = g_zc0p;  N = TH3; }
    else                { W = g_Wih0ep;  bias = nullptr;  C = g_T0p;   N = TH3; }

    __shared__ float As[16][64];
    __shared__ float Bs[16][64];
    int bm = blockIdx.y * 64, bn = blockIdx.x * 64;
    int tid = threadIdx.x;
    int tx = tid & 15, ty = tid >> 4;
    float acc[4][4] = {};

    for (int kt = 0; kt < H_; kt += 16) {
        int r = tid >> 2, kc = (tid & 3) * 4;
        float4 va = *(const float4*)(A + (size_t)(bm + r) * H_ + kt + kc);
        float4 vb = *(const float4*)(W + (size_t)(bn + r) * H_ + kt + kc);
        As[kc + 0][r] = va.x; As[kc + 1][r] = va.y; As[kc + 2][r] = va.z; As[kc + 3][r] = va.w;
        Bs[kc + 0][r] = vb.x; Bs[kc + 1][r] = vb.y; Bs[kc + 2][r] = vb.z; Bs[kc + 3][r] = vb.w;
        __syncthreads();
#pragma unroll
        for (int kk = 0; kk < 16; kk++) {
            float a[4], b[4];
            *(float4*)a = *(const float4*)&As[kk][ty * 4];
            *(float4*)b = *(const float4*)&Bs[kk][tx * 4];
#pragma unroll
            for (int i = 0; i < 4; i++)
#pragma unroll
                for (int j = 0; j < 4; j++) acc[i][j] += a[i] * b[j];
        }
        __syncthreads();
    }
#pragma unroll
    for (int i = 0; i < 4; i++) {
        int row = bm + ty * 4 + i;
#pragma unroll
        for (int j = 0; j < 4; j++) {
            int col = bn + tx * 4 + j;
            float v = acc[i][j] + (bias ? bias[col] : 0.0f);
            C[(size_t)row * N + col] = v;
            if (C2) C2[(size_t)row * N + col] = v;
        }
    }
}

// ============================================================================
// layer0_k: fused gh0 GEMM (64 active rows x 16 h) + GRU epilogue, row-gathered.
// ============================================================================
#define ASTR 68
#define BSTR 50

__global__ void __launch_bounds__(64) layer0_k(int p) {
    int nact = g_nact;
    int bm = blockIdx.y * 64;
    if (bm >= nact) return;
    const float* __restrict__ hcur  = g_h0[p ^ 1];
    float*       __restrict__ hnext = g_h0[p];

    __shared__ int   sidx[64];
    __shared__ float As[16 * ASTR];
    __shared__ float Bs[16 * BSTR];

    int tid = threadIdx.x;
    sidx[tid] = (bm + tid < nact) ? g_active[bm + tid] : g_active[bm];
    int j0 = blockIdx.x * 16;
    int c0 = j0 * 3;
    int rg = (tid >> 3) * 8;
    int cg = (tid & 7) * 6;

    float acc[8][6] = {};

    for (int kt = 0; kt < H_; kt += 16) {
        __syncthreads();
#pragma unroll
        for (int pp = 0; pp < 4; pp++) {
            int r = (tid >> 2) + 16 * pp, kc = (tid & 3) * 4;
            float4 v = *(const float4*)(hcur + (size_t)sidx[r] * H_ + kt + kc);
            As[(kc + 0) * ASTR + r] = v.x;
            As[(kc + 1) * ASTR + r] = v.y;
            As[(kc + 2) * ASTR + r] = v.z;
            As[(kc + 3) * ASTR + r] = v.w;
        }
#pragma unroll
        for (int s = 0; s < 3; s++) {
            int i = tid + 64 * s;
            int col = i >> 2, kc = (i & 3) * 4;
            float4 v = *(const float4*)(g_Whh0p + (size_t)(c0 + col) * H_ + kt + kc);
            Bs[(kc + 0) * BSTR + col] = v.x;
            Bs[(kc + 1) * BSTR + col] = v.y;
            Bs[(kc + 2) * BSTR + col] = v.z;
            Bs[(kc + 3) * BSTR + col] = v.w;
        }
        __syncthreads();
#pragma unroll
        for (int kk = 0; kk < 16; kk++) {
            float a[8], b[6];
            *(float4*)&a[0] = *(const float4*)&As[kk * ASTR + rg];
            *(float4*)&a[4] = *(const float4*)&As[kk * ASTR + rg + 4];
            *(float2*)&b[0] = *(const float2*)&Bs[kk * BSTR + cg];
            *(float2*)&b[2] = *(const float2*)&Bs[kk * BSTR + cg + 2];
            *(float2*)&b[4] = *(const float2*)&Bs[kk * BSTR + cg + 4];
#pragma unroll
            for (int i = 0; i < 8; i++)
#pragma unroll
                for (int j = 0; j < 6; j++) acc[i][j] += a[i] * b[j];
        }
    }
    // fused GRU epilogue (2 complete gate triples per thread), masked by nact
#pragma unroll
    for (int i = 0; i < 8; i++) {
        int slot = rg + i;
        if (bm + slot >= nact) break;
        int b = sidx[slot];
        int wt = g_w[b];
        const float* Trow = &g_T0p[wt * TH3];
        const float* Zrow = &g_zc0p[(size_t)b * TH3];
#pragma unroll
        for (int hh = 0; hh < 2; hh++) {
            int j = j0 + (tid & 7) * 2 + hh;
            int c = j * 3;
            float gi0 = Trow[c]     + Zrow[c];
            float gi1 = Trow[c + 1] + Zrow[c + 1];
            float gi2 = Trow[c + 2] + Zrow[c + 2];
            float gh0 = acc[i][hh * 3 + 0] + g_bhh0p[c];
            float gh1 = acc[i][hh * 3 + 1] + g_bhh0p[c + 1];
            float gh2 = acc[i][hh * 3 + 2] + g_bhh0p[c + 2];
            float rgate = sigmoidf_(gi0 + gh0);
            float zgate = sigmoidf_(gi1 + gh1);
            float nn = tanhf_(gi2 + rgate * gh2);
            float hp = hcur[(size_t)b * H_ + j];
            hnext[(size_t)b * H_ + j] = (1.0f - zgate) * nn + zgate * hp;
        }
    }
}

// ============================================================================
// layer1_k: GEMM into position-indexed scratch, row-gathered A.
// z=0: gi = h_l0 @ Wih1p^T ; z=1: gh = h1 @ Whh1p^T
// ============================================================================
__global__ void __launch_bounds__(64) layer1_k(int p) {
    int nact = g_nact;
    int bm = blockIdx.y * 64;
    if (bm >= nact) return;
    int z = blockIdx.z;
    const float* __restrict__ Amat = z ? g_h1[p ^ 1] : g_h0[p];
    const float* __restrict__ Wmat = z ? g_Whh1p : g_Wih1p;
    float*       __restrict__ Cdst = z ? g_gh : g_gi;

    __shared__ int   sidx[64];
    __shared__ float As[16 * ASTR];
    __shared__ float Bs[16 * BSTR];

    int tid = threadIdx.x;
    sidx[tid] = (bm + tid < nact) ? g_active[bm + tid] : g_active[bm];
    int c0 = blockIdx.x * 48;
    int rg = (tid >> 3) * 8;
    int cg = (tid & 7) * 6;

    float acc[8][6] = {};

    for (int kt = 0; kt < H_; kt += 16) {
        __syncthreads();
#pragma unroll
        for (int pp = 0; pp < 4; pp++) {
            int r = (tid >> 2) + 16 * pp, kc = (tid & 3) * 4;
            float4 v = *(const float4*)(Amat + (size_t)sidx[r] * H_ + kt + kc);
            As[(kc + 0) * ASTR + r] = v.x;
            As[(kc + 1) * ASTR + r] = v.y;
            As[(kc + 2) * ASTR + r] = v.z;
            As[(kc + 3) * ASTR + r] = v.w;
        }
#pragma unroll
        for (int s = 0; s < 3; s++) {
            int i = tid + 64 * s;
            int col = i >> 2, kc = (i & 3) * 4;
            float4 v = *(const float4*)(Wmat + (size_t)(c0 + col) * H_ + kt + kc);
            Bs[(kc + 0) * BSTR + col] = v.x;
            Bs[(kc + 1) * BSTR + col] = v.y;
            Bs[(kc + 2) * BSTR + col] = v.z;
            Bs[(kc + 3) * BSTR + col] = v.w;
        }
        __syncthreads();
#pragma unroll
        for (int kk = 0; kk < 16; kk++) {
            float a[8], b[6];
            *(float4*)&a[0] = *(const float4*)&As[kk * ASTR + rg];
            *(float4*)&a[4] = *(const float4*)&As[kk * ASTR + rg + 4];
            *(float2*)&b[0] = *(const float2*)&Bs[kk * BSTR + cg];
            *(float2*)&b[2] = *(const float2*)&Bs[kk * BSTR + cg + 2];
            *(float2*)&b[4] = *(const float2*)&Bs[kk * BSTR + cg + 4];
#pragma unroll
            for (int i = 0; i < 8; i++)
#pragma unroll
                for (int j = 0; j < 6; j++) acc[i][j] += a[i] * b[j];
        }
    }
    // position-indexed store (slots >= nact write garbage into unused scratch: harmless)
#pragma unroll
    for (int i = 0; i < 8; i++) {
        size_t o = (size_t)(bm + rg + i) * TH3 + c0 + cg;
        *(float2*)&Cdst[o]     = make_float2(acc[i][0], acc[i][1]);
        *(float2*)&Cdst[o + 2] = make_float2(acc[i][2], acc[i][3]);
        *(float2*)&Cdst[o + 4] = make_float2(acc[i][4], acc[i][5]);
    }
}

// ============================================================================
// fuse_k: layer1 GRU epilogue + logits GEMM + argmax + token logic + eos retirement
// ============================================================================
__global__ void __launch_bounds__(256) fuse_k(int p, const float* __restrict__ out_b,
                                              float* __restrict__ xout,
                                              float* __restrict__ endp, int step) {
    int nact = g_nact;
    int b0 = blockIdx.x * 16;
    if (b0 >= nact) return;

    __shared__ int   sidx[16];
    __shared__ float Hs[16 * H_];       // 32 KB
    __shared__ float Ls[16][129];
    int tid = threadIdx.x;
    const float* __restrict__ hprev = g_h1[p ^ 1];
    float*       __restrict__ hnew  = g_h1[p];

    if (tid < 16) sidx[tid] = (b0 + tid < nact) ? g_active[b0 + tid] : -1;
    __syncthreads();

    // phase 1: GRU epilogue for slots b0..b0+15
#pragma unroll
    for (int s = 0; s < 32; s++) {
        int idx = tid + 256 * s;
        int row = idx >> 9, j = idx & 511;
        int tb = sidx[row];
        if (tb < 0) { Hs[row * H_ + j] = 0.0f; continue; }
        int c = j * 3;
        size_t o = (size_t)(b0 + row) * TH3 + c;
        float gi0 = g_gi[o]     + g_bi1p[c];
        float gi1 = g_gi[o + 1] + g_bi1p[c + 1];
        float gi2 = g_gi[o + 2] + g_bi1p[c + 2];
        float gh0 = g_gh[o]     + g_bh1p[c];
        float gh1 = g_gh[o + 1] + g_bh1p[c + 1];
        float gh2 = g_gh[o + 2] + g_bh1p[c + 2];
        float rgate = sigmoidf_(gi0 + gh0);
        float zgate = sigmoidf_(gi1 + gh1);
        float nn = tanhf_(gi2 + rgate * gh2);
        float hp = hprev[(size_t)tb * H_ + j];
        float hv = (1.0f - zgate) * nn + zgate * hp;
        Hs[row * H_ + j] = hv;
        hnew[(size_t)tb * H_ + j] = hv;
    }
    __syncthreads();

    // phase 2: logits GEMM
    int vt = tid & 127, half = tid >> 7;
    float acc[8];
#pragma unroll
    for (int r = 0; r < 8; r++) acc[r] = 0.0f;
    for (int k = 0; k < H_; k += 4) {
        float w0 = g_outWt[(k + 0) * V_ + vt];
        float w1 = g_outWt[(k + 1) * V_ + vt];
        float w2 = g_outWt[(k + 2) * V_ + vt];
        float w3 = g_outWt[(k + 3) * V_ + vt];
#pragma unroll
        for (int r = 0; r < 8; r++) {
            float4 hv = *(const float4*)&Hs[(half * 8 + r) * H_ + k];
            acc[r] += hv.x * w0 + hv.y * w1 + hv.z * w2 + hv.w * w3;
        }
    }
    float bb = out_b[vt];
#pragma unroll
    for (int r = 0; r < 8; r++) Ls[half * 8 + r][vt] = acc[r] + bb;
    __syncthreads();

    // phase 3: argmax + token/eos bookkeeping (all listed rows are live: eos==0)
    if (tid < 16) {
        int tb = sidx[tid];
        if (tb >= 0) {
            const float* row = Ls[tid];
            float best = row[0];
            int bi = 0;
            for (int v = 1; v < V_; v++) {
                float xv = row[v];
                if (xv > best) { best = xv; bi = v; }
            }
            xout[tb * MAXLEN + step] = (float)bi;
            g_w[tb] = bi;
            if (bi == 2) {
                if (endp) endp[tb] = (float)(step + 1);
                g_eos[tb] = 1;
                for (int t2 = step + 1; t2 < MAXLEN; t2++)
                    xout[tb * MAXLEN + t2] = 0.0f;   // retire row: rest of output is zeros
            }
        }
    }
}

// ------------------------- launch -------------------------
extern "C" void kernel_launch(void* const* d_in, const int* in_sizes, int n_in,
                              void* d_out, int out_size) {
    static const int want[14] = {
        B_ * D_, V_ * H_, H_ * D_, H_,
        TH3 * (H_ + D_), TH3 * H_, TH3, TH3,
        TH3 * H_, TH3 * H_, TH3, TH3,
        V_ * H_, V_
    };
    const float* in[14];
    bool used[14] = {};
    bool ok = (n_in >= 14);
    for (int i = 0; i < 14 && ok; i++) {
        int found = -1;
        for (int j = 0; j < 14; j++) {
            if (!used[j] && in_sizes[j] == want[i]) { found = j; break; }
        }
        if (found < 0) { ok = false; break; }
        used[found] = true;
        in[i] = (const float*)d_in[found];
    }
    if (!ok) {
        for (int i = 0; i < 14; i++) in[i] = (const float*)d_in[i];
    }
    const float* z     = in[0];
    const float* lat_W = in[2];
    const float* lat_b = in[3];
    const float* out_b = in[13];

    float* xout = (float*)d_out;
    float* endp = nullptr;
    if (out_size >= B_ * MAXLEN + B_) {
        endp = xout + (out_size - B_);
    }

    permute_kernel<<<(TH3 * H_ + 255) / 256, 256>>>(in[4], in[5], in[8], in[9],
                                                    in[6], in[7], in[10], in[11], in[12]);
    init_state_kernel<<<(B_ + 255) / 256, 256>>>(xout, endp);
    gemm_init_kernel<<<dim3(H_ / 64, B_ / 64), 256>>>(z, lat_W, lat_b, 0);
    gemm_init_kernel<<<dim3(TH3 / 64, B_ / 64), 256>>>(z, nullptr, nullptr, 1);
    gemm_init_kernel<<<dim3(TH3 / 64, V_ / 64), 256>>>(in[1], nullptr, nullptr, 2);

    for (int s = 1; s < MAXLEN; s++) {
        int p = s & 1;
        layer0_k<<<dim3(H_ / 16, B_ / 64), 64>>>(p);
        layer1_k<<<dim3(TH3 / 48, B_ / 64, 2), 64>>>(p);
        fuse_k<<<B_ / 16, 256>>>(p, out_b, xout, endp, s);
        compact_k<<<1, 1024>>>();
    }
}

// round 10
// speedup vs baseline: 1.0543x; 1.0543x over previous
#include <cuda_runtime.h>
#include <math.h>
#include <stdint.h>

#define B_     4096
#define D_     512
#define H_     512
#define V_     128
#define MAXLEN 100
#define TH3    1536   // 3*H

// ------------------------- persistent device scratch -------------------------
__device__ float g_h0[2][B_ * H_];
__device__ float g_h1[2][B_ * H_];
__device__ float g_zc0p[B_ * TH3];        // z @ Wih0[:,H:]^T + bih0 (gate-interleaved)
__device__ float g_T0p[V_ * TH3];         // emb @ Wih0[:,:H]^T (gate-interleaved)
__device__ float g_Whh0p[TH3 * H_];       // permuted: row j*3+g = Whh0[g*H+j]
__device__ float g_Wih1p[TH3 * H_];
__device__ float g_Whh1p[TH3 * H_];
__device__ float g_Wih0ep[TH3 * H_];
__device__ float g_Wih0zp[TH3 * H_];
__device__ float g_bhh0p[TH3];
__device__ float g_bi1p[TH3];
__device__ float g_bh1p[TH3];
__device__ float g_bih0p[TH3];
__device__ float g_outWt[H_ * V_];
__device__ int   g_w[B_];
__device__ int   g_eos[B_];

// --------- accurate, fast-math-immune exp / sigmoid / tanh (identical to R3 pass) ---------
__device__ __forceinline__ float exp_acc(float x) {
    x = fminf(fmaxf(x, -87.0f), 88.0f);
    float k = rintf(x * 1.4426950408889634f);
    float f = fmaf(k, -0.693359375f, x);
    f = fmaf(k, 2.12194440e-4f, f);
    float z = f * f;
    float p = 1.9875691500e-4f;
    p = fmaf(p, f, 1.3981999507e-3f);
    p = fmaf(p, f, 8.3334519073e-3f);
    p = fmaf(p, f, 4.1665795894e-2f);
    p = fmaf(p, f, 1.6666665459e-1f);
    p = fmaf(p, f, 5.0000001201e-1f);
    float y = fmaf(p, z, f) + 1.0f;
    return __int_as_float(__float_as_int(y) + (((int)k) << 23));
}
__device__ __forceinline__ float sigmoidf_(float x) { return 1.0f / (1.0f + exp_acc(-x)); }
__device__ __forceinline__ float tanhf_(float x) {
    float e = exp_acc(2.0f * x);
    return (e - 1.0f) / (e + 1.0f);
}

// ------------------------- init: weight permutation -------------------------
__global__ void permute_kernel(const float* __restrict__ Wih0,
                               const float* __restrict__ Whh0,
                               const float* __restrict__ Wih1,
                               const float* __restrict__ Whh1,
                               const float* __restrict__ bih0,
                               const float* __restrict__ bhh0,
                               const float* __restrict__ bih1,
                               const float* __restrict__ bhh1,
                               const float* __restrict__ outW) {
    int idx = blockIdx.x * blockDim.x + threadIdx.x;
    if (idx < TH3 * H_) {
        int c = idx / H_;
        int k = idx - c * H_;
        int j = c / 3, g = c - 3 * (c / 3);
        int src = g * H_ + j;
        g_Whh0p[idx]  = Whh0[src * H_ + k];
        g_Wih1p[idx]  = Wih1[src * H_ + k];
        g_Whh1p[idx]  = Whh1[src * H_ + k];
        g_Wih0ep[idx] = Wih0[src * (H_ + D_) + k];
        g_Wih0zp[idx] = Wih0[src * (H_ + D_) + H_ + k];
        if (k == 0) {
            g_bhh0p[c] = bhh0[src];
            g_bi1p[c]  = bih1[src];
            g_bh1p[c]  = bhh1[src];
            g_bih0p[c] = bih0[src];
        }
    }
    if (idx < H_ * V_) {
        int k = idx / V_, v = idx - k * V_;
        g_outWt[idx] = outW[v * H_ + k];
    }
}

__global__ void init_state_kernel(float* __restrict__ xout, float* __restrict__ endp) {
    int b = blockIdx.x * blockDim.x + threadIdx.x;
    if (b < B_) {
        g_w[b]   = 1;
        g_eos[b] = 0;
        if (endp) endp[b] = (float)MAXLEN;
        xout[b * MAXLEN] = 1.0f;
    }
}

// ------------------------- init GEMMs (fp32 FFMA, one-time; identical to R3) -------------------------
__global__ void __launch_bounds__(256) gemm_init_kernel(const float* __restrict__ A,
                                                        const float* __restrict__ Wext,
                                                        const float* __restrict__ biasext,
                                                        int mode) {
    const float* W;
    const float* bias;
    float* C;
    float* C2 = nullptr;
    int N;
    if (mode == 0)      { W = Wext;      bias = biasext;  C = g_h0[0]; C2 = g_h1[0]; N = H_;  }
    else if (mode == 1) { W = g_Wih0zp;  bias = g_bih0p;  C = g_zc0p;  N = TH3; }
    else                { W = g_Wih0ep;  bias = nullptr;  C = g_T0p;   N = TH3; }

    __shared__ float As[16][64];
    __shared__ float Bs[16][64];
    int bm = blockIdx.y * 64, bn = blockIdx.x * 64;
    int tid = threadIdx.x;
    int tx = tid & 15, ty = tid >> 4;
    float acc[4][4] = {};

    for (int kt = 0; kt < H_; kt += 16) {
        int r = tid >> 2, kc = (tid & 3) * 4;
        float4 va = *(const float4*)(A + (size_t)(bm + r) * H_ + kt + kc);
        float4 vb = *(const float4*)(W + (size_t)(bn + r) * H_ + kt + kc);
        As[kc + 0][r] = va.x; As[kc + 1][r] = va.y; As[kc + 2][r] = va.z; As[kc + 3][r] = va.w;
        Bs[kc + 0][r] = vb.x; Bs[kc + 1][r] = vb.y; Bs[kc + 2][r] = vb.z; Bs[kc + 3][r] = vb.w;
        __syncthreads();
#pragma unroll
        for (int kk = 0; kk < 16; kk++) {
            float a[4], b[4];
            *(float4*)a = *(const float4*)&As[kk][ty * 4];
            *(float4*)b = *(const float4*)&Bs[kk][tx * 4];
#pragma unroll
            for (int i = 0; i < 4; i++)
#pragma unroll
                for (int j = 0; j < 4; j++) acc[i][j] += a[i] * b[j];
        }
        __syncthreads();
    }
#pragma unroll
    for (int i = 0; i < 4; i++) {
        int row = bm + ty * 4 + i;
#pragma unroll
        for (int j = 0; j < 4; j++) {
            int col = bn + tx * 4 + j;
            float v = acc[i][j] + (bias ? bias[col] : 0.0f);
            C[(size_t)row * N + col] = v;
            if (C2) C2[(size_t)row * N + col] = v;
        }
    }
}

// ============================================================================
// layer0_k: fused gh0 GEMM (64 rows x 16 h) + GRU epilogue (identical to R8).
// ============================================================================
#define ASTR 68
#define BSTR 50

__global__ void __launch_bounds__(64) layer0_k(int p) {
    const float* __restrict__ hcur  = g_h0[p ^ 1];
    float*       __restrict__ hnext = g_h0[p];

    __shared__ float As[16 * ASTR];
    __shared__ float Bs[16 * BSTR];

    int tid = threadIdx.x;
    int bm = blockIdx.y * 64;
    int j0 = blockIdx.x * 16;
    int c0 = j0 * 3;
    int rg = (tid >> 3) * 8;       // row group base (0..56)
    int cg = (tid & 7) * 6;        // col group base (0..42)

    float acc[8][6] = {};

    for (int kt = 0; kt < H_; kt += 16) {
        __syncthreads();
#pragma unroll
        for (int pp = 0; pp < 4; pp++) {
            int r = (tid >> 2) + 16 * pp, kc = (tid & 3) * 4;
            float4 v = *(const float4*)(hcur + (size_t)(bm + r) * H_ + kt + kc);
            As[(kc + 0) * ASTR + r] = v.x;
            As[(kc + 1) * ASTR + r] = v.y;
            As[(kc + 2) * ASTR + r] = v.z;
            As[(kc + 3) * ASTR + r] = v.w;
        }
#pragma unroll
        for (int s = 0; s < 3; s++) {
            int i = tid + 64 * s;
            int col = i >> 2, kc = (i & 3) * 4;
            float4 v = *(const float4*)(g_Whh0p + (size_t)(c0 + col) * H_ + kt + kc);
            Bs[(kc + 0) * BSTR + col] = v.x;
            Bs[(kc + 1) * BSTR + col] = v.y;
            Bs[(kc + 2) * BSTR + col] = v.z;
            Bs[(kc + 3) * BSTR + col] = v.w;
        }
        __syncthreads();
#pragma unroll
        for (int kk = 0; kk < 16; kk++) {
            float a[8], b[6];
            *(float4*)&a[0] = *(const float4*)&As[kk * ASTR + rg];
            *(float4*)&a[4] = *(const float4*)&As[kk * ASTR + rg + 4];
            *(float2*)&b[0] = *(const float2*)&Bs[kk * BSTR + cg];
            *(float2*)&b[2] = *(const float2*)&Bs[kk * BSTR + cg + 2];
            *(float2*)&b[4] = *(const float2*)&Bs[kk * BSTR + cg + 4];
#pragma unroll
            for (int i = 0; i < 8; i++)
#pragma unroll
                for (int j = 0; j < 6; j++) acc[i][j] += a[i] * b[j];
        }
    }
    // fused GRU epilogue (2 complete gate triples per thread)
#pragma unroll
    for (int i = 0; i < 8; i++) {
        int b = bm + rg + i;
        int wt = g_w[b];
        const float* Trow = &g_T0p[wt * TH3];
        const float* Zrow = &g_zc0p[(size_t)b * TH3];
#pragma unroll
        for (int hh = 0; hh < 2; hh++) {
            int j = j0 + (tid & 7) * 2 + hh;
            int c = j * 3;
            float gi0 = Trow[c]     + Zrow[c];
            float gi1 = Trow[c + 1] + Zrow[c + 1];
            float gi2 = Trow[c + 2] + Zrow[c + 2];
            float gh0 = acc[i][hh * 3 + 0] + g_bhh0p[c];
            float gh1 = acc[i][hh * 3 + 1] + g_bhh0p[c + 1];
            float gh2 = acc[i][hh * 3 + 2] + g_bhh0p[c + 2];
            float rgate = sigmoidf_(gi0 + gh0);
            float zgate = sigmoidf_(gi1 + gh1);
            float nn = tanhf_(gi2 + rgate * gh2);
            float hp = hcur[(size_t)b * H_ + j];
            hnext[(size_t)b * H_ + j] = (1.0f - zgate) * nn + zgate * hp;
        }
    }
}

// ============================================================================
// layer1_k (dual GEMM + fused GRU epilogue, no scratch):
//   gi = h_l0 @ Wih1p^T, gh = h1 @ Whh1p^T on the SAME 64x48 tile,
//   then h1' computed directly from registers.
// ============================================================================
__global__ void __launch_bounds__(64) layer1_k(int p) {
    const float* __restrict__ x     = g_h0[p];        // h_l0
    const float* __restrict__ hcur  = g_h1[p ^ 1];
    float*       __restrict__ hnext = g_h1[p];

    __shared__ float As1[16 * ASTR];
    __shared__ float As2[16 * ASTR];
    __shared__ float Bs1[16 * BSTR];
    __shared__ float Bs2[16 * BSTR];

    int tid = threadIdx.x;
    int bm = blockIdx.y * 64;
    int j0 = blockIdx.x * 16;
    int c0 = j0 * 3;
    int rg = (tid >> 3) * 8;
    int cg = (tid & 7) * 6;

    float acc_i[8][6] = {};
    float acc_h[8][6] = {};

    for (int kt = 0; kt < H_; kt += 16) {
        __syncthreads();
#pragma unroll
        for (int pp = 0; pp < 4; pp++) {
            int r = (tid >> 2) + 16 * pp, kc = (tid & 3) * 4;
            float4 vx = *(const float4*)(x    + (size_t)(bm + r) * H_ + kt + kc);
            float4 vh = *(const float4*)(hcur + (size_t)(bm + r) * H_ + kt + kc);
            As1[(kc + 0) * ASTR + r] = vx.x;
            As1[(kc + 1) * ASTR + r] = vx.y;
            As1[(kc + 2) * ASTR + r] = vx.z;
            As1[(kc + 3) * ASTR + r] = vx.w;
            As2[(kc + 0) * ASTR + r] = vh.x;
            As2[(kc + 1) * ASTR + r] = vh.y;
            As2[(kc + 2) * ASTR + r] = vh.z;
            As2[(kc + 3) * ASTR + r] = vh.w;
        }
#pragma unroll
        for (int s = 0; s < 3; s++) {
            int i = tid + 64 * s;
            int col = i >> 2, kc = (i & 3) * 4;
            size_t g = (size_t)(c0 + col) * H_ + kt + kc;
            float4 vi = *(const float4*)(g_Wih1p + g);
            float4 vh = *(const float4*)(g_Whh1p + g);
            Bs1[(kc + 0) * BSTR + col] = vi.x;
            Bs1[(kc + 1) * BSTR + col] = vi.y;
            Bs1[(kc + 2) * BSTR + col] = vi.z;
            Bs1[(kc + 3) * BSTR + col] = vi.w;
            Bs2[(kc + 0) * BSTR + col] = vh.x;
            Bs2[(kc + 1) * BSTR + col] = vh.y;
            Bs2[(kc + 2) * BSTR + col] = vh.z;
            Bs2[(kc + 3) * BSTR + col] = vh.w;
        }
        __syncthreads();
#pragma unroll
        for (int kk = 0; kk < 16; kk++) {
            float a1[8], a2[8], b1[6], b2[6];
            *(float4*)&a1[0] = *(const float4*)&As1[kk * ASTR + rg];
            *(float4*)&a1[4] = *(const float4*)&As1[kk * ASTR + rg + 4];
            *(float4*)&a2[0] = *(const float4*)&As2[kk * ASTR + rg];
            *(float4*)&a2[4] = *(const float4*)&As2[kk * ASTR + rg + 4];
            *(float2*)&b1[0] = *(const float2*)&Bs1[kk * BSTR + cg];
            *(float2*)&b1[2] = *(const float2*)&Bs1[kk * BSTR + cg + 2];
            *(float2*)&b1[4] = *(const float2*)&Bs1[kk * BSTR + cg + 4];
            *(float2*)&b2[0] = *(const float2*)&Bs2[kk * BSTR + cg];
            *(float2*)&b2[2] = *(const float2*)&Bs2[kk * BSTR + cg + 2];
            *(float2*)&b2[4] = *(const float2*)&Bs2[kk * BSTR + cg + 4];
#pragma unroll
            for (int i = 0; i < 8; i++)
#pragma unroll
                for (int j = 0; j < 6; j++) {
                    acc_i[i][j] += a1[i] * b1[j];
                    acc_h[i][j] += a2[i] * b2[j];
                }
        }
    }
    // fused GRU epilogue straight from registers
#pragma unroll
    for (int i = 0; i < 8; i++) {
        int b = bm + rg + i;
#pragma unroll
        for (int hh = 0; hh < 2; hh++) {
            int j = j0 + (tid & 7) * 2 + hh;
            int c = j * 3;
            float gi0 = acc_i[i][hh * 3 + 0] + g_bi1p[c];
            float gi1 = acc_i[i][hh * 3 + 1] + g_bi1p[c + 1];
            float gi2 = acc_i[i][hh * 3 + 2] + g_bi1p[c + 2];
            float gh0 = acc_h[i][hh * 3 + 0] + g_bh1p[c];
            float gh1 = acc_h[i][hh * 3 + 1] + g_bh1p[c + 1];
            float gh2 = acc_h[i][hh * 3 + 2] + g_bh1p[c + 2];
            float rgate = sigmoidf_(gi0 + gh0);
            float zgate = sigmoidf_(gi1 + gh1);
            float nn = tanhf_(gi2 + rgate * gh2);
            float hp = hcur[(size_t)b * H_ + j];
            hnext[(size_t)b * H_ + j] = (1.0f - zgate) * nn + zgate * hp;
        }
    }
}

// ------------------------- logits + argmax + token logic (R3-style) -------------------------
__global__ void __launch_bounds__(128) logits_kernel(int p, const float* __restrict__ out_b,
                                                     float* __restrict__ xout,
                                                     float* __restrict__ endp, int step) {
    const float* __restrict__ h = g_h1[p];
    __shared__ float Hs[16 * H_];
    __shared__ float Ls[16][129];
    int b0 = blockIdx.x * 16;
    int tid = threadIdx.x;

    const float4* src = (const float4*)(h + (size_t)b0 * H_);
    float4* dst = (float4*)Hs;
    for (int i = tid; i < 16 * H_ / 4; i += 128) dst[i] = src[i];
    __syncthreads();

    float acc[16];
#pragma unroll
    for (int r = 0; r < 16; r++) acc[r] = 0.0f;

    for (int k = 0; k < H_; k += 4) {
        float w0 = g_outWt[(k + 0) * V_ + tid];
        float w1 = g_outWt[(k + 1) * V_ + tid];
        float w2 = g_outWt[(k + 2) * V_ + tid];
        float w3 = g_outWt[(k + 3) * V_ + tid];
#pragma unroll
        for (int r = 0; r < 16; r++) {
            float4 hv = *(const float4*)&Hs[r * H_ + k];
            acc[r] += hv.x * w0 + hv.y * w1 + hv.z * w2 + hv.w * w3;
        }
    }
    float bb = out_b[tid];
#pragma unroll
    for (int r = 0; r < 16; r++) Ls[r][tid] = acc[r] + bb;
    __syncthreads();

    if (tid < 16) {
        int b = b0 + tid;
        const float* row = Ls[tid];
        float best = row[0];
        int bi = 0;
        for (int v = 1; v < V_; v++) {
            float xv = row[v];
            if (xv > best) { best = xv; bi = v; }
        }
        int eo = g_eos[b];
        xout[b * MAXLEN + step] = eo ? 0.0f : (float)bi;
        if (!eo && bi == 2) {
            if (endp) endp[b] = (float)(step + 1);
            g_eos[b] = 1;
        }
        g_w[b] = bi;
    }
}

// ------------------------- launch -------------------------
extern "C" void kernel_launch(void* const* d_in, const int* in_sizes, int n_in,
                              void* d_out, int out_size) {
    static const int want[14] = {
        B_ * D_, V_ * H_, H_ * D_, H_,
        TH3 * (H_ + D_), TH3 * H_, TH3, TH3,
        TH3 * H_, TH3 * H_, TH3, TH3,
        V_ * H_, V_
    };
    const float* in[14];
    bool used[14] = {};
    bool ok = (n_in >= 14);
    for (int i = 0; i < 14 && ok; i++) {
        int found = -1;
        for (int j = 0; j < 14; j++) {
            if (!used[j] && in_sizes[j] == want[i]) { found = j; break; }
        }
        if (found < 0) { ok = false; break; }
        used[found] = true;
        in[i] = (const float*)d_in[found];
    }
    if (!ok) {
        for (int i = 0; i < 14; i++) in[i] = (const float*)d_in[i];
    }
    const float* z     = in[0];
    const float* lat_W = in[2];
    const float* lat_b = in[3];
    const float* out_b = in[13];

    float* xout = (float*)d_out;
    float* endp = nullptr;
    if (out_size >= B_ * MAXLEN + B_) {
        endp = xout + (out_size - B_);
    }

    permute_kernel<<<(TH3 * H_ + 255) / 256, 256>>>(in[4], in[5], in[8], in[9],
                                                    in[6], in[7], in[10], in[11], in[12]);
    init_state_kernel<<<(B_ + 255) / 256, 256>>>(xout, endp);
    gemm_init_kernel<<<dim3(H_ / 64, B_ / 64), 256>>>(z, lat_W, lat_b, 0);
    gemm_init_kernel<<<dim3(TH3 / 64, B_ / 64), 256>>>(z, nullptr, nullptr, 1);
    gemm_init_kernel<<<dim3(TH3 / 64, V_ / 64), 256>>>(in[1], nullptr, nullptr, 2);

    for (int s = 1; s < MAXLEN; s++) {
        int p = s & 1;
        layer0_k<<<dim3(H_ / 16, B_ / 64), 64>>>(p);
        layer1_k<<<dim3(H_ / 16, B_ / 64), 64>>>(p);
        logits_kernel<<<B_ / 16, 128>>>(p, out_b, xout, endp, s);
    }
}

// round 11
// speedup vs baseline: 1.1885x; 1.1273x over previous
#include <cuda_runtime.h>
#include <math.h>
#include <stdint.h>

#define B_     4096
#define D_     512
#define H_     512
#define V_     128
#define MAXLEN 100
#define TH3    1536   // 3*H

// ------------------------- persistent device scratch -------------------------
__device__ float g_h0[2][B_ * H_];
__device__ float g_h1[2][B_ * H_];
__device__ float g_zc0p[B_ * TH3];        // z @ Wih0[:,H:]^T + bih0 (gate-interleaved)
__device__ float g_T0p[V_ * TH3];         // emb @ Wih0[:,:H]^T (gate-interleaved)
__device__ float g_Whh0p[TH3 * H_];       // permuted: row j*3+g = Whh0[g*H+j]
__device__ float g_Wih1p[TH3 * H_];
__device__ float g_Whh1p[TH3 * H_];
__device__ float g_Wih0ep[TH3 * H_];
__device__ float g_Wih0zp[TH3 * H_];
__device__ float g_bhh0p[TH3];
__device__ float g_bi1p[TH3];
__device__ float g_bh1p[TH3];
__device__ float g_bih0p[TH3];
__device__ float g_outWt[H_ * V_];
__device__ float g_gi[B_ * TH3];          // layer1 input-GEMM scratch
__device__ float g_gh[B_ * TH3];          // layer1 hidden-GEMM scratch
__device__ int   g_w[B_];
__device__ int   g_eos[B_];

// --------- accurate, fast-math-immune exp / sigmoid / tanh (identical to R3 pass) ---------
__device__ __forceinline__ float exp_acc(float x) {
    x = fminf(fmaxf(x, -87.0f), 88.0f);
    float k = rintf(x * 1.4426950408889634f);
    float f = fmaf(k, -0.693359375f, x);
    f = fmaf(k, 2.12194440e-4f, f);
    float z = f * f;
    float p = 1.9875691500e-4f;
    p = fmaf(p, f, 1.3981999507e-3f);
    p = fmaf(p, f, 8.3334519073e-3f);
    p = fmaf(p, f, 4.1665795894e-2f);
    p = fmaf(p, f, 1.6666665459e-1f);
    p = fmaf(p, f, 5.0000001201e-1f);
    float y = fmaf(p, z, f) + 1.0f;
    return __int_as_float(__float_as_int(y) + (((int)k) << 23));
}
__device__ __forceinline__ float sigmoidf_(float x) { return 1.0f / (1.0f + exp_acc(-x)); }
__device__ __forceinline__ float tanhf_(float x) {
    float e = exp_acc(2.0f * x);
    return (e - 1.0f) / (e + 1.0f);
}

// ------------------------- init: weight permutation -------------------------
__global__ void permute_kernel(const float* __restrict__ Wih0,
                               const float* __restrict__ Whh0,
                               const float* __restrict__ Wih1,
                               const float* __restrict__ Whh1,
                               const float* __restrict__ bih0,
                               const float* __restrict__ bhh0,
                               const float* __restrict__ bih1,
                               const float* __restrict__ bhh1,
                               const float* __restrict__ outW) {
    int idx = blockIdx.x * blockDim.x + threadIdx.x;
    if (idx < TH3 * H_) {
        int c = idx / H_;
        int k = idx - c * H_;
        int j = c / 3, g = c - 3 * (c / 3);
        int src = g * H_ + j;
        g_Whh0p[idx]  = Whh0[src * H_ + k];
        g_Wih1p[idx]  = Wih1[src * H_ + k];
        g_Whh1p[idx]  = Whh1[src * H_ + k];
        g_Wih0ep[idx] = Wih0[src * (H_ + D_) + k];
        g_Wih0zp[idx] = Wih0[src * (H_ + D_) + H_ + k];
        if (k == 0) {
            g_bhh0p[c] = bhh0[src];
            g_bi1p[c]  = bih1[src];
            g_bh1p[c]  = bhh1[src];
            g_bih0p[c] = bih0[src];
        }
    }
    if (idx < H_ * V_) {
        int k = idx / V_, v = idx - k * V_;
        g_outWt[idx] = outW[v * H_ + k];
    }
}

__global__ void init_state_kernel(float* __restrict__ xout, float* __restrict__ endp) {
    int b = blockIdx.x * blockDim.x + threadIdx.x;
    if (b < B_) {
        g_w[b]   = 1;
        g_eos[b] = 0;
        if (endp) endp[b] = (float)MAXLEN;
        xout[b * MAXLEN] = 1.0f;
    }
}

// ------------------------- init GEMMs (fp32 FFMA, one-time; identical to R3) -------------------------
__global__ void __launch_bounds__(256) gemm_init_kernel(const float* __restrict__ A,
                                                        const float* __restrict__ Wext,
                                                        const float* __restrict__ biasext,
                                                        int mode) {
    const float* W;
    const float* bias;
    float* C;
    float* C2 = nullptr;
    int N;
    if (mode == 0)      { W = Wext;      bias = biasext;  C = g_h0[0]; C2 = g_h1[0]; N = H_;  }
    else if (mode == 1) { W = g_Wih0zp;  bias = g_bih0p;  C = g_zc0p;  N = TH3; }
    else                { W = g_Wih0ep;  bias = nullptr;  C = g_T0p;   N = TH3; }

    __shared__ float As[16][64];
    __shared__ float Bs[16][64];
    int bm = blockIdx.y * 64, bn = blockIdx.x * 64;
    int tid = threadIdx.x;
    int tx = tid & 15, ty = tid >> 4;
    float acc[4][4] = {};

    for (int kt = 0; kt < H_; kt += 16) {
        int r = tid >> 2, kc = (tid & 3) * 4;
        float4 va = *(const float4*)(A + (size_t)(bm + r) * H_ + kt + kc);
        float4 vb = *(const float4*)(W + (size_t)(bn + r) * H_ + kt + kc);
        As[kc + 0][r] = va.x; As[kc + 1][r] = va.y; As[kc + 2][r] = va.z; As[kc + 3][r] = va.w;
        Bs[kc + 0][r] = vb.x; Bs[kc + 1][r] = vb.y; Bs[kc + 2][r] = vb.z; Bs[kc + 3][r] = vb.w;
        __syncthreads();
#pragma unroll
        for (int kk = 0; kk < 16; kk++) {
            float a[4], b[4];
            *(float4*)a = *(const float4*)&As[kk][ty * 4];
            *(float4*)b = *(const float4*)&Bs[kk][tx * 4];
#pragma unroll
            for (int i = 0; i < 4; i++)
#pragma unroll
                for (int j = 0; j < 4; j++) acc[i][j] += a[i] * b[j];
        }
        __syncthreads();
    }
#pragma unroll
    for (int i = 0; i < 4; i++) {
        int row = bm + ty * 4 + i;
#pragma unroll
        for (int j = 0; j < 4; j++) {
            int col = bn + tx * 4 + j;
            float v = acc[i][j] + (bias ? bias[col] : 0.0f);
            C[(size_t)row * N + col] = v;
            if (C2) C2[(size_t)row * N + col] = v;
        }
    }
}

// ============================================================================
// layer0_k: fused gh0 GEMM (64 rows x 16 h) + GRU epilogue (identical to R8).
// ============================================================================
#define ASTR 68
#define BSTR 50

__global__ void __launch_bounds__(64) layer0_k(int p) {
    const float* __restrict__ hcur  = g_h0[p ^ 1];
    float*       __restrict__ hnext = g_h0[p];

    __shared__ float As[16 * ASTR];
    __shared__ float Bs[16 * BSTR];

    int tid = threadIdx.x;
    int bm = blockIdx.y * 64;
    int j0 = blockIdx.x * 16;
    int c0 = j0 * 3;
    int rg = (tid >> 3) * 8;       // row group base (0..56)
    int cg = (tid & 7) * 6;        // col group base (0..42)

    float acc[8][6] = {};

    for (int kt = 0; kt < H_; kt += 16) {
        __syncthreads();
#pragma unroll
        for (int pp = 0; pp < 4; pp++) {
            int r = (tid >> 2) + 16 * pp, kc = (tid & 3) * 4;
            float4 v = *(const float4*)(hcur + (size_t)(bm + r) * H_ + kt + kc);
            As[(kc + 0) * ASTR + r] = v.x;
            As[(kc + 1) * ASTR + r] = v.y;
            As[(kc + 2) * ASTR + r] = v.z;
            As[(kc + 3) * ASTR + r] = v.w;
        }
#pragma unroll
        for (int s = 0; s < 3; s++) {
            int i = tid + 64 * s;
            int col = i >> 2, kc = (i & 3) * 4;
            float4 v = *(const float4*)(g_Whh0p + (size_t)(c0 + col) * H_ + kt + kc);
            Bs[(kc + 0) * BSTR + col] = v.x;
            Bs[(kc + 1) * BSTR + col] = v.y;
            Bs[(kc + 2) * BSTR + col] = v.z;
            Bs[(kc + 3) * BSTR + col] = v.w;
        }
        __syncthreads();
#pragma unroll
        for (int kk = 0; kk < 16; kk++) {
            float a[8], b[6];
            *(float4*)&a[0] = *(const float4*)&As[kk * ASTR + rg];
            *(float4*)&a[4] = *(const float4*)&As[kk * ASTR + rg + 4];
            *(float2*)&b[0] = *(const float2*)&Bs[kk * BSTR + cg];
            *(float2*)&b[2] = *(const float2*)&Bs[kk * BSTR + cg + 2];
            *(float2*)&b[4] = *(const float2*)&Bs[kk * BSTR + cg + 4];
#pragma unroll
            for (int i = 0; i < 8; i++)
#pragma unroll
                for (int j = 0; j < 6; j++) acc[i][j] += a[i] * b[j];
        }
    }
    // fused GRU epilogue (2 complete gate triples per thread)
#pragma unroll
    for (int i = 0; i < 8; i++) {
        int b = bm + rg + i;
        int wt = g_w[b];
        const float* Trow = &g_T0p[wt * TH3];
        const float* Zrow = &g_zc0p[(size_t)b * TH3];
#pragma unroll
        for (int hh = 0; hh < 2; hh++) {
            int j = j0 + (tid & 7) * 2 + hh;
            int c = j * 3;
            float gi0 = Trow[c]     + Zrow[c];
            float gi1 = Trow[c + 1] + Zrow[c + 1];
            float gi2 = Trow[c + 2] + Zrow[c + 2];
            float gh0 = acc[i][hh * 3 + 0] + g_bhh0p[c];
            float gh1 = acc[i][hh * 3 + 1] + g_bhh0p[c + 1];
            float gh2 = acc[i][hh * 3 + 2] + g_bhh0p[c + 2];
            float rgate = sigmoidf_(gi0 + gh0);
            float zgate = sigmoidf_(gi1 + gh1);
            float nn = tanhf_(gi2 + rgate * gh2);
            float hp = hcur[(size_t)b * H_ + j];
            hnext[(size_t)b * H_ + j] = (1.0f - zgate) * nn + zgate * hp;
        }
    }
}

// ============================================================================
// layer1_k: plain GEMM into scratch (identical to R8).
// z=0: gi = h_l0 @ Wih1p^T; z=1: gh = h1 @ Whh1p^T
// ============================================================================
__global__ void __launch_bounds__(64) layer1_k(int p) {
    int z = blockIdx.z;
    const float* __restrict__ Amat = z ? g_h1[p ^ 1] : g_h0[p];
    const float* __restrict__ Wmat = z ? g_Whh1p : g_Wih1p;
    float*       __restrict__ Cdst = z ? g_gh : g_gi;

    __shared__ float As[16 * ASTR];
    __shared__ float Bs[16 * BSTR];

    int tid = threadIdx.x;
    int bm = blockIdx.y * 64;
    int c0 = blockIdx.x * 48;
    int rg = (tid >> 3) * 8;
    int cg = (tid & 7) * 6;

    float acc[8][6] = {};

    for (int kt = 0; kt < H_; kt += 16) {
        __syncthreads();
#pragma unroll
        for (int pp = 0; pp < 4; pp++) {
            int r = (tid >> 2) + 16 * pp, kc = (tid & 3) * 4;
            float4 v = *(const float4*)(Amat + (size_t)(bm + r) * H_ + kt + kc);
            As[(kc + 0) * ASTR + r] = v.x;
            As[(kc + 1) * ASTR + r] = v.y;
            As[(kc + 2) * ASTR + r] = v.z;
            As[(kc + 3) * ASTR + r] = v.w;
        }
#pragma unroll
        for (int s = 0; s < 3; s++) {
            int i = tid + 64 * s;
            int col = i >> 2, kc = (i & 3) * 4;
            float4 v = *(const float4*)(Wmat + (size_t)(c0 + col) * H_ + kt + kc);
            Bs[(kc + 0) * BSTR + col] = v.x;
            Bs[(kc + 1) * BSTR + col] = v.y;
            Bs[(kc + 2) * BSTR + col] = v.z;
            Bs[(kc + 3) * BSTR + col] = v.w;
        }
        __syncthreads();
#pragma unroll
        for (int kk = 0; kk < 16; kk++) {
            float a[8], b[6];
            *(float4*)&a[0] = *(const float4*)&As[kk * ASTR + rg];
            *(float4*)&a[4] = *(const float4*)&As[kk * ASTR + rg + 4];
            *(float2*)&b[0] = *(const float2*)&Bs[kk * BSTR + cg];
            *(float2*)&b[2] = *(const float2*)&Bs[kk * BSTR + cg + 2];
            *(float2*)&b[4] = *(const float2*)&Bs[kk * BSTR + cg + 4];
#pragma unroll
            for (int i = 0; i < 8; i++)
#pragma unroll
                for (int j = 0; j < 6; j++) acc[i][j] += a[i] * b[j];
        }
    }
#pragma unroll
    for (int i = 0; i < 8; i++) {
        size_t o = (size_t)(bm + rg + i) * TH3 + c0 + cg;
        *(float2*)&Cdst[o]     = make_float2(acc[i][0], acc[i][1]);
        *(float2*)&Cdst[o + 2] = make_float2(acc[i][2], acc[i][3]);
        *(float2*)&Cdst[o + 4] = make_float2(acc[i][4], acc[i][5]);
    }
}

// ============================================================================
// fuse_k: layer1 GRU epilogue + logits GEMM + argmax + token logic.
// Re-tiled vs R8: 512 blocks x 256 threads, 8 rows/block (better SM balance);
// per-(row,v) arithmetic chains unchanged -> bit-identical.
// ============================================================================
__global__ void __launch_bounds__(256) fuse_k(int p, const float* __restrict__ out_b,
                                              float* __restrict__ xout,
                                              float* __restrict__ endp, int step) {
    __shared__ float Hs[8 * H_];        // 16 KB
    __shared__ float Ls[8][129];
    int b0 = blockIdx.x * 8;
    int tid = threadIdx.x;
    const float* __restrict__ hprev = g_h1[p ^ 1];
    float*       __restrict__ hnew  = g_h1[p];

    // phase 1: GRU epilogue for rows b0..b0+7
#pragma unroll
    for (int s = 0; s < 16; s++) {
        int idx = tid + 256 * s;
        int row = idx >> 9, j = idx & 511;
        int b = b0 + row;
        int c = j * 3;
        size_t o = (size_t)b * TH3 + c;
        float gi0 = g_gi[o]     + g_bi1p[c];
        float gi1 = g_gi[o + 1] + g_bi1p[c + 1];
        float gi2 = g_gi[o + 2] + g_bi1p[c + 2];
        float gh0 = g_gh[o]     + g_bh1p[c];
        float gh1 = g_gh[o + 1] + g_bh1p[c + 1];
        float gh2 = g_gh[o + 2] + g_bh1p[c + 2];
        float rgate = sigmoidf_(gi0 + gh0);
        float zgate = sigmoidf_(gi1 + gh1);
        float nn = tanhf_(gi2 + rgate * gh2);
        float hp = hprev[(size_t)b * H_ + j];
        float hv = (1.0f - zgate) * nn + zgate * hp;
        Hs[row * H_ + j] = hv;
        hnew[(size_t)b * H_ + j] = hv;
    }
    __syncthreads();

    // phase 2: logits GEMM (two quads of 4 rows; vt = vocab index)
    int vt = tid & 127, half = tid >> 7;
    float acc[4];
#pragma unroll
    for (int r = 0; r < 4; r++) acc[r] = 0.0f;
    for (int k = 0; k < H_; k += 4) {
        float w0 = g_outWt[(k + 0) * V_ + vt];
        float w1 = g_outWt[(k + 1) * V_ + vt];
        float w2 = g_outWt[(k + 2) * V_ + vt];
        float w3 = g_outWt[(k + 3) * V_ + vt];
#pragma unroll
        for (int r = 0; r < 4; r++) {
            float4 hv = *(const float4*)&Hs[(half * 4 + r) * H_ + k];
            acc[r] += hv.x * w0 + hv.y * w1 + hv.z * w2 + hv.w * w3;
        }
    }
    float bb = out_b[vt];
#pragma unroll
    for (int r = 0; r < 4; r++) Ls[half * 4 + r][vt] = acc[r] + bb;
    __syncthreads();

    // phase 3: argmax + token/eos bookkeeping
    if (tid < 8) {
        int b = b0 + tid;
        const float* row = Ls[tid];
        float best = row[0];
        int bi = 0;
        for (int v = 1; v < V_; v++) {
            float xv = row[v];
            if (xv > best) { best = xv; bi = v; }
        }
        int eo = g_eos[b];
        xout[b * MAXLEN + step] = eo ? 0.0f : (float)bi;
        if (!eo && bi == 2) {
            if (endp) endp[b] = (float)(step + 1);
            g_eos[b] = 1;
        }
        g_w[b] = bi;
    }
}

// ------------------------- launch -------------------------
extern "C" void kernel_launch(void* const* d_in, const int* in_sizes, int n_in,
                              void* d_out, int out_size) {
    static const int want[14] = {
        B_ * D_, V_ * H_, H_ * D_, H_,
        TH3 * (H_ + D_), TH3 * H_, TH3, TH3,
        TH3 * H_, TH3 * H_, TH3, TH3,
        V_ * H_, V_
    };
    const float* in[14];
    bool used[14] = {};
    bool ok = (n_in >= 14);
    for (int i = 0; i < 14 && ok; i++) {
        int found = -1;
        for (int j = 0; j < 14; j++) {
            if (!used[j] && in_sizes[j] == want[i]) { found = j; break; }
        }
        if (found < 0) { ok = false; break; }
        used[found] = true;
        in[i] = (const float*)d_in[found];
    }
    if (!ok) {
        for (int i = 0; i < 14; i++) in[i] = (const float*)d_in[i];
    }
    const float* z     = in[0];
    const float* lat_W = in[2];
    const float* lat_b = in[3];
    const float* out_b = in[13];

    float* xout = (float*)d_out;
    float* endp = nullptr;
    if (out_size >= B_ * MAXLEN + B_) {
        endp = xout + (out_size - B_);
    }

    permute_kernel<<<(TH3 * H_ + 255) / 256, 256>>>(in[4], in[5], in[8], in[9],
                                                    in[6], in[7], in[10], in[11], in[12]);
    init_state_kernel<<<(B_ + 255) / 256, 256>>>(xout, endp);
    gemm_init_kernel<<<dim3(H_ / 64, B_ / 64), 256>>>(z, lat_W, lat_b, 0);
    gemm_init_kernel<<<dim3(TH3 / 64, B_ / 64), 256>>>(z, nullptr, nullptr, 1);
    gemm_init_kernel<<<dim3(TH3 / 64, V_ / 64), 256>>>(in[1], nullptr, nullptr, 2);

    for (int s = 1; s < MAXLEN; s++) {
        int p = s & 1;
        layer0_k<<<dim3(H_ / 16, B_ / 64), 64>>>(p);
        layer1_k<<<dim3(TH3 / 48, B_ / 64, 2), 64>>>(p);
        fuse_k<<<B_ / 8, 256>>>(p, out_b, xout, endp, s);
    }
}

// round 13
// speedup vs baseline: 1.1892x; 1.0006x over previous
#include <cuda_runtime.h>
#include <math.h>
#include <stdint.h>

#define B_     4096
#define D_     512
#define H_     512
#define V_     128
#define MAXLEN 100
#define TH3    1536   // 3*H

// ------------------------- persistent device scratch -------------------------
__device__ float g_h0[2][B_ * H_];
__device__ float g_h1[2][B_ * H_];
__device__ float g_zc0p[B_ * TH3];        // z @ Wih0[:,H:]^T + bih0 (gate-interleaved)
__device__ float g_T0p[V_ * TH3];         // emb @ Wih0[:,:H]^T (gate-interleaved)
__device__ float g_Whh0p[TH3 * H_];       // permuted: row j*3+g = Whh0[g*H+j]
__device__ float g_Wih1p[TH3 * H_];
__device__ float g_Whh1p[TH3 * H_];
__device__ float g_Wih0ep[TH3 * H_];
__device__ float g_Wih0zp[TH3 * H_];
__device__ float g_bhh0p[TH3];
__device__ float g_bi1p[TH3];
__device__ float g_bh1p[TH3];
__device__ float g_bih0p[TH3];
__device__ float g_outWt[H_ * V_];
__device__ float g_gi[B_ * TH3];          // layer1 input-GEMM scratch
__device__ float g_gh[B_ * TH3];          // layer1 hidden-GEMM scratch
__device__ int   g_w[B_];
__device__ int   g_eos[B_];

// --------- accurate, fast-math-immune exp / sigmoid / tanh (identical to R3 pass) ---------
__device__ __forceinline__ float exp_acc(float x) {
    x = fminf(fmaxf(x, -87.0f), 88.0f);
    float k = rintf(x * 1.4426950408889634f);
    float f = fmaf(k, -0.693359375f, x);
    f = fmaf(k, 2.12194440e-4f, f);
    float z = f * f;
    float p = 1.9875691500e-4f;
    p = fmaf(p, f, 1.3981999507e-3f);
    p = fmaf(p, f, 8.3334519073e-3f);
    p = fmaf(p, f, 4.1665795894e-2f);
    p = fmaf(p, f, 1.6666665459e-1f);
    p = fmaf(p, f, 5.0000001201e-1f);
    float y = fmaf(p, z, f) + 1.0f;
    return __int_as_float(__float_as_int(y) + (((int)k) << 23));
}
__device__ __forceinline__ float sigmoidf_(float x) { return 1.0f / (1.0f + exp_acc(-x)); }
__device__ __forceinline__ float tanhf_(float x) {
    float e = exp_acc(2.0f * x);
    return (e - 1.0f) / (e + 1.0f);
}

// ------------------------- init: weight permutation -------------------------
__global__ void permute_kernel(const float* __restrict__ Wih0,
                               const float* __restrict__ Whh0,
                               const float* __restrict__ Wih1,
                               const float* __restrict__ Whh1,
                               const float* __restrict__ bih0,
                               const float* __restrict__ bhh0,
                               const float* __restrict__ bih1,
                               const float* __restrict__ bhh1,
                               const float* __restrict__ outW) {
    int idx = blockIdx.x * blockDim.x + threadIdx.x;
    if (idx < TH3 * H_) {
        int c = idx / H_;
        int k = idx - c * H_;
        int j = c / 3, g = c - 3 * (c / 3);
        int src = g * H_ + j;
        g_Whh0p[idx]  = Whh0[src * H_ + k];
        g_Wih1p[idx]  = Wih1[src * H_ + k];
        g_Whh1p[idx]  = Whh1[src * H_ + k];
        g_Wih0ep[idx] = Wih0[src * (H_ + D_) + k];
        g_Wih0zp[idx] = Wih0[src * (H_ + D_) + H_ + k];
        if (k == 0) {
            g_bhh0p[c] = bhh0[src];
            g_bi1p[c]  = bih1[src];
            g_bh1p[c]  = bhh1[src];
            g_bih0p[c] = bih0[src];
        }
    }
    if (idx < H_ * V_) {
        int k = idx / V_, v = idx - k * V_;
        g_outWt[idx] = outW[v * H_ + k];
    }
}

__global__ void init_state_kernel(float* __restrict__ xout, float* __restrict__ endp) {
    int b = blockIdx.x * blockDim.x + threadIdx.x;
    if (b < B_) {
        g_w[b]   = 1;
        g_eos[b] = 0;
        if (endp) endp[b] = (float)MAXLEN;
        xout[b * MAXLEN] = 1.0f;
    }
}

#define ASTR 68
#define BSTR 50
#define BSTR2 68   // was 66: kk*66*4 is only 8B-aligned for odd kk -> LDS.128 trap. 68*4=272 is 16B-aligned.

// ------------------------- init GEMMs: fine 64-thread tiles (64x64, 8x8/thread) --------
// Per-output-element accumulation is k-ascending -> bit-identical to prior versions.
// mode 0: C=g_h0[0](+g_h1[0]) = z @ lat_W^T + lat_b, N=512
// mode 1: C=g_zc0p = z @ Wih0zp^T + bih0p, N=1536
// mode 2: C=g_T0p  = emb @ Wih0ep^T, N=1536 (M=128)
__global__ void __launch_bounds__(64) gemm_init_k(const float* __restrict__ A,
                                                  const float* __restrict__ Wext,
                                                  const float* __restrict__ biasext,
                                                  int mode) {
    const float* W;
    const float* bias;
    float* C;
    float* C2 = nullptr;
    int N;
    if (mode == 0)      { W = Wext;      bias = biasext;  C = g_h0[0]; C2 = g_h1[0]; N = H_;  }
    else if (mode == 1) { W = g_Wih0zp;  bias = g_bih0p;  C = g_zc0p;  N = TH3; }
    else                { W = g_Wih0ep;  bias = nullptr;  C = g_T0p;   N = TH3; }

    __shared__ float As[16 * ASTR];
    __shared__ float Bs[16 * BSTR2];

    int tid = threadIdx.x;
    int bm = blockIdx.y * 64;
    int bn = blockIdx.x * 64;
    int rg = (tid >> 3) * 8;       // row group base (0..56)
    int cg = (tid & 7) * 8;        // col group base (0..56)

    float acc[8][8] = {};

    for (int kt = 0; kt < H_; kt += 16) {
        __syncthreads();
#pragma unroll
        for (int pp = 0; pp < 4; pp++) {
            int r = (tid >> 2) + 16 * pp, kc = (tid & 3) * 4;
            float4 v = *(const float4*)(A + (size_t)(bm + r) * H_ + kt + kc);
            As[(kc + 0) * ASTR + r] = v.x;
            As[(kc + 1) * ASTR + r] = v.y;
            As[(kc + 2) * ASTR + r] = v.z;
            As[(kc + 3) * ASTR + r] = v.w;
        }
#pragma unroll
        for (int s = 0; s < 4; s++) {
            int i = tid + 64 * s;
            int col = i >> 2, kc = (i & 3) * 4;
            float4 v = *(const float4*)(W + (size_t)(bn + col) * H_ + kt + kc);
            Bs[(kc + 0) * BSTR2 + col] = v.x;
            Bs[(kc + 1) * BSTR2 + col] = v.y;
            Bs[(kc + 2) * BSTR2 + col] = v.z;
            Bs[(kc + 3) * BSTR2 + col] = v.w;
        }
        __syncthreads();
#pragma unroll
        for (int kk = 0; kk < 16; kk++) {
            float a[8], b[8];
            *(float4*)&a[0] = *(const float4*)&As[kk * ASTR + rg];
            *(float4*)&a[4] = *(const float4*)&As[kk * ASTR + rg + 4];
            *(float4*)&b[0] = *(const float4*)&Bs[kk * BSTR2 + cg];
            *(float4*)&b[4] = *(const float4*)&Bs[kk * BSTR2 + cg + 4];
#pragma unroll
            for (int i = 0; i < 8; i++)
#pragma unroll
                for (int j = 0; j < 8; j++) acc[i][j] += a[i] * b[j];
        }
    }
#pragma unroll
    for (int i = 0; i < 8; i++) {
        int row = bm + rg + i;
#pragma unroll
        for (int j = 0; j < 8; j++) {
            int col = bn + cg + j;
            float v = acc[i][j] + (bias ? bias[col] : 0.0f);
            C[(size_t)row * N + col] = v;
            if (C2) C2[(size_t)row * N + col] = v;
        }
    }
}

// ============================================================================
// layer0_k: fused gh0 GEMM (64 rows x 16 h) + GRU epilogue (identical to R11).
// ============================================================================
__global__ void __launch_bounds__(64) layer0_k(int p) {
    const float* __restrict__ hcur  = g_h0[p ^ 1];
    float*       __restrict__ hnext = g_h0[p];

    __shared__ float As[16 * ASTR];
    __shared__ float Bs[16 * BSTR];

    int tid = threadIdx.x;
    int bm = blockIdx.y * 64;
    int j0 = blockIdx.x * 16;
    int c0 = j0 * 3;
    int rg = (tid >> 3) * 8;       // row group base (0..56)
    int cg = (tid & 7) * 6;        // col group base (0..42)

    float acc[8][6] = {};

    for (int kt = 0; kt < H_; kt += 16) {
        __syncthreads();
#pragma unroll
        for (int pp = 0; pp < 4; pp++) {
            int r = (tid >> 2) + 16 * pp, kc = (tid & 3) * 4;
            float4 v = *(const float4*)(hcur + (size_t)(bm + r) * H_ + kt + kc);
            As[(kc + 0) * ASTR + r] = v.x;
            As[(kc + 1) * ASTR + r] = v.y;
            As[(kc + 2) * ASTR + r] = v.z;
            As[(kc + 3) * ASTR + r] = v.w;
        }
#pragma unroll
        for (int s = 0; s < 3; s++) {
            int i = tid + 64 * s;
            int col = i >> 2, kc = (i & 3) * 4;
            float4 v = *(const float4*)(g_Whh0p + (size_t)(c0 + col) * H_ + kt + kc);
            Bs[(kc + 0) * BSTR + col] = v.x;
            Bs[(kc + 1) * BSTR + col] = v.y;
            Bs[(kc + 2) * BSTR + col] = v.z;
            Bs[(kc + 3) * BSTR + col] = v.w;
        }
        __syncthreads();
#pragma unroll
        for (int kk = 0; kk < 16; kk++) {
            float a[8], b[6];
            *(float4*)&a[0] = *(const float4*)&As[kk * ASTR + rg];
            *(float4*)&a[4] = *(const float4*)&As[kk * ASTR + rg + 4];
            *(float2*)&b[0] = *(const float2*)&Bs[kk * BSTR + cg];
            *(float2*)&b[2] = *(const float2*)&Bs[kk * BSTR + cg + 2];
            *(float2*)&b[4] = *(const float2*)&Bs[kk * BSTR + cg + 4];
#pragma unroll
            for (int i = 0; i < 8; i++)
#pragma unroll
                for (int j = 0; j < 6; j++) acc[i][j] += a[i] * b[j];
        }
    }
    // fused GRU epilogue (2 complete gate triples per thread)
#pragma unroll
    for (int i = 0; i < 8; i++) {
        int b = bm + rg + i;
        int wt = g_w[b];
        const float* Trow = &g_T0p[wt * TH3];
        const float* Zrow = &g_zc0p[(size_t)b * TH3];
#pragma unroll
        for (int hh = 0; hh < 2; hh++) {
            int j = j0 + (tid & 7) * 2 + hh;
            int c = j * 3;
            float gi0 = Trow[c]     + Zrow[c];
            float gi1 = Trow[c + 1] + Zrow[c + 1];
            float gi2 = Trow[c + 2] + Zrow[c + 2];
            float gh0 = acc[i][hh * 3 + 0] + g_bhh0p[c];
            float gh1 = acc[i][hh * 3 + 1] + g_bhh0p[c + 1];
            float gh2 = acc[i][hh * 3 + 2] + g_bhh0p[c + 2];
            float rgate = sigmoidf_(gi0 + gh0);
            float zgate = sigmoidf_(gi1 + gh1);
            float nn = tanhf_(gi2 + rgate * gh2);
            float hp = hcur[(size_t)b * H_ + j];
            hnext[(size_t)b * H_ + j] = (1.0f - zgate) * nn + zgate * hp;
        }
    }
}

// ============================================================================
// layer1_k: plain GEMM into scratch (identical to R11).
// z=0: gi = h_l0 @ Wih1p^T; z=1: gh = h1 @ Whh1p^T
// ============================================================================
__global__ void __launch_bounds__(64) layer1_k(int p) {
    int z = blockIdx.z;
    const float* __restrict__ Amat = z ? g_h1[p ^ 1] : g_h0[p];
    const float* __restrict__ Wmat = z ? g_Whh1p : g_Wih1p;
    float*       __restrict__ Cdst = z ? g_gh : g_gi;

    __shared__ float As[16 * ASTR];
    __shared__ float Bs[16 * BSTR];

    int tid = threadIdx.x;
    int bm = blockIdx.y * 64;
    int c0 = blockIdx.x * 48;
    int rg = (tid >> 3) * 8;
    int cg = (tid & 7) * 6;

    float acc[8][6] = {};

    for (int kt = 0; kt < H_; kt += 16) {
        __syncthreads();
#pragma unroll
        for (int pp = 0; pp < 4; pp++) {
            int r = (tid >> 2) + 16 * pp, kc = (tid & 3) * 4;
            float4 v = *(const float4*)(Amat + (size_t)(bm + r) * H_ + kt + kc);
            As[(kc + 0) * ASTR + r] = v.x;
            As[(kc + 1) * ASTR + r] = v.y;
            As[(kc + 2) * ASTR + r] = v.z;
            As[(kc + 3) * ASTR + r] = v.w;
        }
#pragma unroll
        for (int s = 0; s < 3; s++) {
            int i = tid + 64 * s;
            int col = i >> 2, kc = (i & 3) * 4;
            float4 v = *(const float4*)(Wmat + (size_t)(c0 + col) * H_ + kt + kc);
            Bs[(kc + 0) * BSTR + col] = v.x;
            Bs[(kc + 1) * BSTR + col] = v.y;
            Bs[(kc + 2) * BSTR + col] = v.z;
            Bs[(kc + 3) * BSTR + col] = v.w;
        }
        __syncthreads();
#pragma unroll
        for (int kk = 0; kk < 16; kk++) {
            float a[8], b[6];
            *(float4*)&a[0] = *(const float4*)&As[kk * ASTR + rg];
            *(float4*)&a[4] = *(const float4*)&As[kk * ASTR + rg + 4];
            *(float2*)&b[0] = *(const float2*)&Bs[kk * BSTR + cg];
            *(float2*)&b[2] = *(const float2*)&Bs[kk * BSTR + cg + 2];
            *(float2*)&b[4] = *(const float2*)&Bs[kk * BSTR + cg + 4];
#pragma unroll
            for (int i = 0; i < 8; i++)
#pragma unroll
                for (int j = 0; j < 6; j++) acc[i][j] += a[i] * b[j];
        }
    }
#pragma unroll
    for (int i = 0; i < 8; i++) {
        size_t o = (size_t)(bm + rg + i) * TH3 + c0 + cg;
        *(float2*)&Cdst[o]     = make_float2(acc[i][0], acc[i][1]);
        *(float2*)&Cdst[o + 2] = make_float2(acc[i][2], acc[i][3]);
        *(float2*)&Cdst[o + 4] = make_float2(acc[i][4], acc[i][5]);
    }
}

// ============================================================================
// fuse_k: layer1 GRU epilogue + logits GEMM + argmax + token logic (identical to R11).
// 512 blocks x 256 threads, 8 rows/block.
// ============================================================================
__global__ void __launch_bounds__(256) fuse_k(int p, const float* __restrict__ out_b,
                                              float* __restrict__ xout,
                                              float* __restrict__ endp, int step) {
    __shared__ float Hs[8 * H_];        // 16 KB
    __shared__ float Ls[8][129];
    int b0 = blockIdx.x * 8;
    int tid = threadIdx.x;
    const float* __restrict__ hprev = g_h1[p ^ 1];
    float*       __restrict__ hnew  = g_h1[p];

    // phase 1: GRU epilogue for rows b0..b0+7
#pragma unroll
    for (int s = 0; s < 16; s++) {
        int idx = tid + 256 * s;
        int row = idx >> 9, j = idx & 511;
        int b = b0 + row;
        int c = j * 3;
        size_t o = (size_t)b * TH3 + c;
        float gi0 = g_gi[o]     + g_bi1p[c];
        float gi1 = g_gi[o + 1] + g_bi1p[c + 1];
        float gi2 = g_gi[o + 2] + g_bi1p[c + 2];
        float gh0 = g_gh[o]     + g_bh1p[c];
        float gh1 = g_gh[o + 1] + g_bh1p[c + 1];
        float gh2 = g_gh[o + 2] + g_bh1p[c + 2];
        float rgate = sigmoidf_(gi0 + gh0);
        float zgate = sigmoidf_(gi1 + gh1);
        float nn = tanhf_(gi2 + rgate * gh2);
        float hp = hprev[(size_t)b * H_ + j];
        float hv = (1.0f - zgate) * nn + zgate * hp;
        Hs[row * H_ + j] = hv;
        hnew[(size_t)b * H_ + j] = hv;
    }
    __syncthreads();

    // phase 2: logits GEMM (two quads of 4 rows; vt = vocab index)
    int vt = tid & 127, half = tid >> 7;
    float acc[4];
#pragma unroll
    for (int r = 0; r < 4; r++) acc[r] = 0.0f;
    for (int k = 0; k < H_; k += 4) {
        float w0 = g_outWt[(k + 0) * V_ + vt];
        float w1 = g_outWt[(k + 1) * V_ + vt];
        float w2 = g_outWt[(k + 2) * V_ + vt];
        float w3 = g_outWt[(k + 3) * V_ + vt];
#pragma unroll
        for (int r = 0; r < 4; r++) {
            float4 hv = *(const float4*)&Hs[(half * 4 + r) * H_ + k];
            acc[r] += hv.x * w0 + hv.y * w1 + hv.z * w2 + hv.w * w3;
        }
    }
    float bb = out_b[vt];
#pragma unroll
    for (int r = 0; r < 4; r++) Ls[half * 4 + r][vt] = acc[r] + bb;
    __syncthreads();

    // phase 3: argmax + token/eos bookkeeping
    if (tid < 8) {
        int b = b0 + tid;
        const float* row = Ls[tid];
        float best = row[0];
        int bi = 0;
        for (int v = 1; v < V_; v++) {
            float xv = row[v];
            if (xv > best) { best = xv; bi = v; }
        }
        int eo = g_eos[b];
        xout[b * MAXLEN + step] = eo ? 0.0f : (float)bi;
        if (!eo && bi == 2) {
            if (endp) endp[b] = (float)(step + 1);
            g_eos[b] = 1;
        }
        g_w[b] = bi;
    }
}

// ------------------------- launch -------------------------
extern "C" void kernel_launch(void* const* d_in, const int* in_sizes, int n_in,
                              void* d_out, int out_size) {
    static const int want[14] = {
        B_ * D_, V_ * H_, H_ * D_, H_,
        TH3 * (H_ + D_), TH3 * H_, TH3, TH3,
        TH3 * H_, TH3 * H_, TH3, TH3,
        V_ * H_, V_
    };
    const float* in[14];
    bool used[14] = {};
    bool ok = (n_in >= 14);
    for (int i = 0; i < 14 && ok; i++) {
        int found = -1;
        for (int j = 0; j < 14; j++) {
            if (!used[j] && in_sizes[j] == want[i]) { found = j; break; }
        }
        if (found < 0) { ok = false; break; }
        used[found] = true;
        in[i] = (const float*)d_in[found];
    }
    if (!ok) {
        for (int i = 0; i < 14; i++) in[i] = (const float*)d_in[i];
    }
    const float* z     = in[0];
    const float* lat_W = in[2];
    const float* lat_b = in[3];
    const float* out_b = in[13];

    float* xout = (float*)d_out;
    float* endp = nullptr;
    if (out_size >= B_ * MAXLEN + B_) {
        endp = xout + (out_size - B_);
    }

    permute_kernel<<<(TH3 * H_ + 255) / 256, 256>>>(in[4], in[5], in[8], in[9],
                                                    in[6], in[7], in[10], in[11], in[12]);
    init_state_kernel<<<(B_ + 255) / 256, 256>>>(xout, endp);
    gemm_init_k<<<dim3(H_ / 64, B_ / 64), 64>>>(z, lat_W, lat_b, 0);
    gemm_init_k<<<dim3(TH3 / 64, B_ / 64), 64>>>(z, nullptr, nullptr, 1);
    gemm_init_k<<<dim3(TH3 / 64, V_ / 64), 64>>>(in[1], nullptr, nullptr, 2);

    for (int s = 1; s < MAXLEN; s++) {
        int p = s & 1;
        layer0_k<<<dim3(H_ / 16, B_ / 64), 64>>>(p);
        layer1_k<<<dim3(TH3 / 48, B_ / 64, 2), 64>>>(p);
        fuse_k<<<B_ / 8, 256>>>(p, out_b, xout, endp, s);
    }
}

// round 14
// speedup vs baseline: 1.1900x; 1.0006x over previous
#include <cuda_runtime.h>
#include <math.h>
#include <stdint.h>

#define B_     4096
#define D_     512
#define H_     512
#define V_     128
#define MAXLEN 100
#define TH3    1536   // 3*H

// ------------------------- persistent device scratch -------------------------
__device__ float g_h0[2][B_ * H_];
__device__ float g_h1[2][B_ * H_];
__device__ float g_zc0p[B_ * TH3];        // z @ Wih0[:,H:]^T + bih0 (gate-interleaved)
__device__ float g_T0p[V_ * TH3];         // emb @ Wih0[:,:H]^T (gate-interleaved)
__device__ float g_Whh0p[TH3 * H_];       // permuted: row j*3+g = Whh0[g*H+j]
__device__ float g_Wih1p[TH3 * H_];
__device__ float g_Whh1p[TH3 * H_];
__device__ float g_Wih0ep[TH3 * H_];
__device__ float g_Wih0zp[TH3 * H_];
__device__ float g_bhh0p[TH3];
__device__ float g_bi1p[TH3];
__device__ float g_bh1p[TH3];
__device__ float g_bih0p[TH3];
__device__ float g_outWt[H_ * V_];
__device__ float g_gi[B_ * TH3];          // layer1 input-GEMM scratch
__device__ float g_gh[B_ * TH3];          // layer1 hidden-GEMM scratch
__device__ int   g_w[B_];
__device__ int   g_eos[B_];

// --------- accurate, fast-math-immune exp / sigmoid / tanh (identical to R3 pass) ---------
__device__ __forceinline__ float exp_acc(float x) {
    x = fminf(fmaxf(x, -87.0f), 88.0f);
    float k = rintf(x * 1.4426950408889634f);
    float f = fmaf(k, -0.693359375f, x);
    f = fmaf(k, 2.12194440e-4f, f);
    float z = f * f;
    float p = 1.9875691500e-4f;
    p = fmaf(p, f, 1.3981999507e-3f);
    p = fmaf(p, f, 8.3334519073e-3f);
    p = fmaf(p, f, 4.1665795894e-2f);
    p = fmaf(p, f, 1.6666665459e-1f);
    p = fmaf(p, f, 5.0000001201e-1f);
    float y = fmaf(p, z, f) + 1.0f;
    return __int_as_float(__float_as_int(y) + (((int)k) << 23));
}
__device__ __forceinline__ float sigmoidf_(float x) { return 1.0f / (1.0f + exp_acc(-x)); }
__device__ __forceinline__ float tanhf_(float x) {
    float e = exp_acc(2.0f * x);
    return (e - 1.0f) / (e + 1.0f);
}

// ------------------------- init: weight permutation -------------------------
__global__ void permute_kernel(const float* __restrict__ Wih0,
                               const float* __restrict__ Whh0,
                               const float* __restrict__ Wih1,
                               const float* __restrict__ Whh1,
                               const float* __restrict__ bih0,
                               const float* __restrict__ bhh0,
                               const float* __restrict__ bih1,
                               const float* __restrict__ bhh1,
                               const float* __restrict__ outW) {
    int idx = blockIdx.x * blockDim.x + threadIdx.x;
    if (idx < TH3 * H_) {
        int c = idx / H_;
        int k = idx - c * H_;
        int j = c / 3, g = c - 3 * (c / 3);
        int src = g * H_ + j;
        g_Whh0p[idx]  = Whh0[src * H_ + k];
        g_Wih1p[idx]  = Wih1[src * H_ + k];
        g_Whh1p[idx]  = Whh1[src * H_ + k];
        g_Wih0ep[idx] = Wih0[src * (H_ + D_) + k];
        g_Wih0zp[idx] = Wih0[src * (H_ + D_) + H_ + k];
        if (k == 0) {
            g_bhh0p[c] = bhh0[src];
            g_bi1p[c]  = bih1[src];
            g_bh1p[c]  = bhh1[src];
            g_bih0p[c] = bih0[src];
        }
    }
    if (idx < H_ * V_) {
        int k = idx / V_, v = idx - k * V_;
        g_outWt[idx] = outW[v * H_ + k];
    }
}

__global__ void init_state_kernel(float* __restrict__ xout, float* __restrict__ endp) {
    int b = blockIdx.x * blockDim.x + threadIdx.x;
    if (b < B_) {
        g_w[b]   = 1;
        g_eos[b] = 0;
        if (endp) endp[b] = (float)MAXLEN;
        xout[b * MAXLEN] = 1.0f;
    }
}

#define ASTR 68
#define BSTR 50
#define BSTR2 68

// ------------------------- init GEMMs: 128 threads, 64x64 tile, 8x4/thread --------
// Lower register pressure (acc 32) -> ~28 warps/SM -> latency hidden.
// Per-output-element accumulation is k-ascending -> bit-identical values.
__global__ void __launch_bounds__(128) gemm_init_k(const float* __restrict__ A,
                                                   const float* __restrict__ Wext,
                                                   const float* __restrict__ biasext,
                                                   int mode) {
    const float* W;
    const float* bias;
    float* C;
    float* C2 = nullptr;
    int N;
    if (mode == 0)      { W = Wext;      bias = biasext;  C = g_h0[0]; C2 = g_h1[0]; N = H_;  }
    else if (mode == 1) { W = g_Wih0zp;  bias = g_bih0p;  C = g_zc0p;  N = TH3; }
    else                { W = g_Wih0ep;  bias = nullptr;  C = g_T0p;   N = TH3; }

    __shared__ float As[16 * ASTR];
    __shared__ float Bs[16 * BSTR2];

    int tid = threadIdx.x;
    int bm = blockIdx.y * 64;
    int bn = blockIdx.x * 64;
    int rg = (tid >> 4) * 8;       // 8 row groups of 8
    int cg = (tid & 15) * 4;       // 16 col groups of 4

    float acc[8][4] = {};

    for (int kt = 0; kt < H_; kt += 16) {
        __syncthreads();
#pragma unroll
        for (int pp = 0; pp < 2; pp++) {
            int r = (tid >> 2) + 32 * pp, kc = (tid & 3) * 4;
            float4 v = *(const float4*)(A + (size_t)(bm + r) * H_ + kt + kc);
            As[(kc + 0) * ASTR + r] = v.x;
            As[(kc + 1) * ASTR + r] = v.y;
            As[(kc + 2) * ASTR + r] = v.z;
            As[(kc + 3) * ASTR + r] = v.w;
        }
#pragma unroll
        for (int pp = 0; pp < 2; pp++) {
            int col = (tid >> 2) + 32 * pp, kc = (tid & 3) * 4;
            float4 v = *(const float4*)(W + (size_t)(bn + col) * H_ + kt + kc);
            Bs[(kc + 0) * BSTR2 + col] = v.x;
            Bs[(kc + 1) * BSTR2 + col] = v.y;
            Bs[(kc + 2) * BSTR2 + col] = v.z;
            Bs[(kc + 3) * BSTR2 + col] = v.w;
        }
        __syncthreads();
#pragma unroll
        for (int kk = 0; kk < 16; kk++) {
            float a[8], b[4];
            *(float4*)&a[0] = *(const float4*)&As[kk * ASTR + rg];
            *(float4*)&a[4] = *(const float4*)&As[kk * ASTR + rg + 4];
            *(float4*)&b[0] = *(const float4*)&Bs[kk * BSTR2 + cg];
#pragma unroll
            for (int i = 0; i < 8; i++)
#pragma unroll
                for (int j = 0; j < 4; j++) acc[i][j] += a[i] * b[j];
        }
    }
#pragma unroll
    for (int i = 0; i < 8; i++) {
        int row = bm + rg + i;
#pragma unroll
        for (int j = 0; j < 4; j++) {
            int col = bn + cg + j;
            float v = acc[i][j] + (bias ? bias[col] : 0.0f);
            C[(size_t)row * N + col] = v;
            if (C2) C2[(size_t)row * N + col] = v;
        }
    }
}

// ============================================================================
// step kernel 1 (merged): z=0 -> layer0 fused GEMM+GRU; z=1 -> layer1 gh GEMM.
// Both bodies byte-identical to their R13 kernels; gh depends only on h1[p^1],
// so it runs concurrently with layer0 in one 4096-block launch.
// ============================================================================
__global__ void __launch_bounds__(64) step1_k(int p) {
    __shared__ float As[16 * ASTR];
    __shared__ float Bs[16 * BSTR];
    int tid = threadIdx.x;
    int bm = blockIdx.y * 64;
    int rg = (tid >> 3) * 8;
    int cg = (tid & 7) * 6;

    if (blockIdx.z == 0) {
        // ---- layer0: gh0 GEMM + GRU epilogue ----
        const float* __restrict__ hcur  = g_h0[p ^ 1];
        float*       __restrict__ hnext = g_h0[p];
        int j0 = blockIdx.x * 16;
        int c0 = j0 * 3;

        float acc[8][6] = {};
        for (int kt = 0; kt < H_; kt += 16) {
            __syncthreads();
#pragma unroll
            for (int pp = 0; pp < 4; pp++) {
                int r = (tid >> 2) + 16 * pp, kc = (tid & 3) * 4;
                float4 v = *(const float4*)(hcur + (size_t)(bm + r) * H_ + kt + kc);
                As[(kc + 0) * ASTR + r] = v.x;
                As[(kc + 1) * ASTR + r] = v.y;
                As[(kc + 2) * ASTR + r] = v.z;
                As[(kc + 3) * ASTR + r] = v.w;
            }
#pragma unroll
            for (int s = 0; s < 3; s++) {
                int i = tid + 64 * s;
                int col = i >> 2, kc = (i & 3) * 4;
                float4 v = *(const float4*)(g_Whh0p + (size_t)(c0 + col) * H_ + kt + kc);
                Bs[(kc + 0) * BSTR + col] = v.x;
                Bs[(kc + 1) * BSTR + col] = v.y;
                Bs[(kc + 2) * BSTR + col] = v.z;
                Bs[(kc + 3) * BSTR + col] = v.w;
            }
            __syncthreads();
#pragma unroll
            for (int kk = 0; kk < 16; kk++) {
                float a[8], b[6];
                *(float4*)&a[0] = *(const float4*)&As[kk * ASTR + rg];
                *(float4*)&a[4] = *(const float4*)&As[kk * ASTR + rg + 4];
                *(float2*)&b[0] = *(const float2*)&Bs[kk * BSTR + cg];
                *(float2*)&b[2] = *(const float2*)&Bs[kk * BSTR + cg + 2];
                *(float2*)&b[4] = *(const float2*)&Bs[kk * BSTR + cg + 4];
#pragma unroll
                for (int i = 0; i < 8; i++)
#pragma unroll
                    for (int j = 0; j < 6; j++) acc[i][j] += a[i] * b[j];
            }
        }
#pragma unroll
        for (int i = 0; i < 8; i++) {
            int b = bm + rg + i;
            int wt = g_w[b];
            const float* Trow = &g_T0p[wt * TH3];
            const float* Zrow = &g_zc0p[(size_t)b * TH3];
#pragma unroll
            for (int hh = 0; hh < 2; hh++) {
                int j = j0 + (tid & 7) * 2 + hh;
                int c = j * 3;
                float gi0 = Trow[c]     + Zrow[c];
                float gi1 = Trow[c + 1] + Zrow[c + 1];
                float gi2 = Trow[c + 2] + Zrow[c + 2];
                float gh0 = acc[i][hh * 3 + 0] + g_bhh0p[c];
                float gh1 = acc[i][hh * 3 + 1] + g_bhh0p[c + 1];
                float gh2 = acc[i][hh * 3 + 2] + g_bhh0p[c + 2];
                float rgate = sigmoidf_(gi0 + gh0);
                float zgate = sigmoidf_(gi1 + gh1);
                float nn = tanhf_(gi2 + rgate * gh2);
                float hp = hcur[(size_t)b * H_ + j];
                hnext[(size_t)b * H_ + j] = (1.0f - zgate) * nn + zgate * hp;
            }
        }
    } else {
        // ---- layer1 gh: g_gh = h1 @ Whh1p^T ----
        const float* __restrict__ Amat = g_h1[p ^ 1];
        int c0 = blockIdx.x * 48;

        float acc[8][6] = {};
        for (int kt = 0; kt < H_; kt += 16) {
            __syncthreads();
#pragma unroll
            for (int pp = 0; pp < 4; pp++) {
                int r = (tid >> 2) + 16 * pp, kc = (tid & 3) * 4;
                float4 v = *(const float4*)(Amat + (size_t)(bm + r) * H_ + kt + kc);
                As[(kc + 0) * ASTR + r] = v.x;
                As[(kc + 1) * ASTR + r] = v.y;
                As[(kc + 2) * ASTR + r] = v.z;
                As[(kc + 3) * ASTR + r] = v.w;
            }
#pragma unroll
            for (int s = 0; s < 3; s++) {
                int i = tid + 64 * s;
                int col = i >> 2, kc = (i & 3) * 4;
                float4 v = *(const float4*)(g_Whh1p + (size_t)(c0 + col) * H_ + kt + kc);
                Bs[(kc + 0) * BSTR + col] = v.x;
                Bs[(kc + 1) * BSTR + col] = v.y;
                Bs[(kc + 2) * BSTR + col] = v.z;
                Bs[(kc + 3) * BSTR + col] = v.w;
            }
            __syncthreads();
#pragma unroll
            for (int kk = 0; kk < 16; kk++) {
                float a[8], b[6];
                *(float4*)&a[0] = *(const float4*)&As[kk * ASTR + rg];
                *(float4*)&a[4] = *(const float4*)&As[kk * ASTR + rg + 4];
                *(float2*)&b[0] = *(const float2*)&Bs[kk * BSTR + cg];
                *(float2*)&b[2] = *(const float2*)&Bs[kk * BSTR + cg + 2];
                *(float2*)&b[4] = *(const float2*)&Bs[kk * BSTR + cg + 4];
#pragma unroll
                for (int i = 0; i < 8; i++)
#pragma unroll
                    for (int j = 0; j < 6; j++) acc[i][j] += a[i] * b[j];
            }
        }
#pragma unroll
        for (int i = 0; i < 8; i++) {
            size_t o = (size_t)(bm + rg + i) * TH3 + c0 + cg;
            *(float2*)&g_gh[o]     = make_float2(acc[i][0], acc[i][1]);
            *(float2*)&g_gh[o + 2] = make_float2(acc[i][2], acc[i][3]);
            *(float2*)&g_gh[o + 4] = make_float2(acc[i][4], acc[i][5]);
        }
    }
}

// ============================================================================
// step kernel 2: gi = h_l0 @ Wih1p^T into scratch (R13 layer1_k, z=0 path only)
// ============================================================================
__global__ void __launch_bounds__(64) gi_k(int p) {
    const float* __restrict__ Amat = g_h0[p];

    __shared__ float As[16 * ASTR];
    __shared__ float Bs[16 * BSTR];

    int tid = threadIdx.x;
    int bm = blockIdx.y * 64;
    int c0 = blockIdx.x * 48;
    int rg = (tid >> 3) * 8;
    int cg = (tid & 7) * 6;

    float acc[8][6] = {};

    for (int kt = 0; kt < H_; kt += 16) {
        __syncthreads();
#pragma unroll
        for (int pp = 0; pp < 4; pp++) {
            int r = (tid >> 2) + 16 * pp, kc = (tid & 3) * 4;
            float4 v = *(const float4*)(Amat + (size_t)(bm + r) * H_ + kt + kc);
            As[(kc + 0) * ASTR + r] = v.x;
            As[(kc + 1) * ASTR + r] = v.y;
            As[(kc + 2) * ASTR + r] = v.z;
            As[(kc + 3) * ASTR + r] = v.w;
        }
#pragma unroll
        for (int s = 0; s < 3; s++) {
            int i = tid + 64 * s;
            int col = i >> 2, kc = (i & 3) * 4;
            float4 v = *(const float4*)(g_Wih1p + (size_t)(c0 + col) * H_ + kt + kc);
            Bs[(kc + 0) * BSTR + col] = v.x;
            Bs[(kc + 1) * BSTR + col] = v.y;
            Bs[(kc + 2) * BSTR + col] = v.z;
            Bs[(kc + 3) * BSTR + col] = v.w;
        }
        __syncthreads();
#pragma unroll
        for (int kk = 0; kk < 16; kk++) {
            float a[8], b[6];
            *(float4*)&a[0] = *(const float4*)&As[kk * ASTR + rg];
            *(float4*)&a[4] = *(const float4*)&As[kk * ASTR + rg + 4];
            *(float2*)&b[0] = *(const float2*)&Bs[kk * BSTR + cg];
            *(float2*)&b[2] = *(const float2*)&Bs[kk * BSTR + cg + 2];
            *(float2*)&b[4] = *(const float2*)&Bs[kk * BSTR + cg + 4];
#pragma unroll
            for (int i = 0; i < 8; i++)
#pragma unroll
                for (int j = 0; j < 6; j++) acc[i][j] += a[i] * b[j];
        }
    }
#pragma unroll
    for (int i = 0; i < 8; i++) {
        size_t o = (size_t)(bm + rg + i) * TH3 + c0 + cg;
        *(float2*)&g_gi[o]     = make_float2(acc[i][0], acc[i][1]);
        *(float2*)&g_gi[o + 2] = make_float2(acc[i][2], acc[i][3]);
        *(float2*)&g_gi[o + 4] = make_float2(acc[i][4], acc[i][5]);
    }
}

// ============================================================================
// fuse_k: layer1 GRU epilogue + logits GEMM + argmax + token logic (identical to R13).
// ============================================================================
__global__ void __launch_bounds__(256) fuse_k(int p, const float* __restrict__ out_b,
                                              float* __restrict__ xout,
                                              float* __restrict__ endp, int step) {
    __shared__ float Hs[8 * H_];        // 16 KB
    __shared__ float Ls[8][129];
    int b0 = blockIdx.x * 8;
    int tid = threadIdx.x;
    const float* __restrict__ hprev = g_h1[p ^ 1];
    float*       __restrict__ hnew  = g_h1[p];

#pragma unroll
    for (int s = 0; s < 16; s++) {
        int idx = tid + 256 * s;
        int row = idx >> 9, j = idx & 511;
        int b = b0 + row;
        int c = j * 3;
        size_t o = (size_t)b * TH3 + c;
        float gi0 = g_gi[o]     + g_bi1p[c];
        float gi1 = g_gi[o + 1] + g_bi1p[c + 1];
        float gi2 = g_gi[o + 2] + g_bi1p[c + 2];
        float gh0 = g_gh[o]     + g_bh1p[c];
        float gh1 = g_gh[o + 1] + g_bh1p[c + 1];
        float gh2 = g_gh[o + 2] + g_bh1p[c + 2];
        float rgate = sigmoidf_(gi0 + gh0);
        float zgate = sigmoidf_(gi1 + gh1);
        float nn = tanhf_(gi2 + rgate * gh2);
        float hp = hprev[(size_t)b * H_ + j];
        float hv = (1.0f - zgate) * nn + zgate * hp;
        Hs[row * H_ + j] = hv;
        hnew[(size_t)b * H_ + j] = hv;
    }
    __syncthreads();

    int vt = tid & 127, half = tid >> 7;
    float acc[4];
#pragma unroll
    for (int r = 0; r < 4; r++) acc[r] = 0.0f;
    for (int k = 0; k < H_; k += 4) {
        float w0 = g_outWt[(k + 0) * V_ + vt];
        float w1 = g_outWt[(k + 1) * V_ + vt];
        float w2 = g_outWt[(k + 2) * V_ + vt];
        float w3 = g_outWt[(k + 3) * V_ + vt];
#pragma unroll
        for (int r = 0; r < 4; r++) {
            float4 hv = *(const float4*)&Hs[(half * 4 + r) * H_ + k];
            acc[r] += hv.x * w0 + hv.y * w1 + hv.z * w2 + hv.w * w3;
        }
    }
    float bb = out_b[vt];
#pragma unroll
    for (int r = 0; r < 4; r++) Ls[half * 4 + r][vt] = acc[r] + bb;
    __syncthreads();

    if (tid < 8) {
        int b = b0 + tid;
        const float* row = Ls[tid];
        float best = row[0];
        int bi = 0;
        for (int v = 1; v < V_; v++) {
            float xv = row[v];
            if (xv > best) { best = xv; bi = v; }
        }
        int eo = g_eos[b];
        xout[b * MAXLEN + step] = eo ? 0.0f : (float)bi;
        if (!eo && bi == 2) {
            if (endp) endp[b] = (float)(step + 1);
            g_eos[b] = 1;
        }
        g_w[b] = bi;
    }
}

// ------------------------- launch -------------------------
extern "C" void kernel_launch(void* const* d_in, const int* in_sizes, int n_in,
                              void* d_out, int out_size) {
    static const int want[14] = {
        B_ * D_, V_ * H_, H_ * D_, H_,
        TH3 * (H_ + D_), TH3 * H_, TH3, TH3,
        TH3 * H_, TH3 * H_, TH3, TH3,
        V_ * H_, V_
    };
    const float* in[14];
    bool used[14] = {};
    bool ok = (n_in >= 14);
    for (int i = 0; i < 14 && ok; i++) {
        int found = -1;
        for (int j = 0; j < 14; j++) {
            if (!used[j] && in_sizes[j] == want[i]) { found = j; break; }
        }
        if (found < 0) { ok = false; break; }
        used[found] = true;
        in[i] = (const float*)d_in[found];
    }
    if (!ok) {
        for (int i = 0; i < 14; i++) in[i] = (const float*)d_in[i];
    }
    const float* z     = in[0];
    const float* lat_W = in[2];
    const float* lat_b = in[3];
    const float* out_b = in[13];

    float* xout = (float*)d_out;
    float* endp = nullptr;
    if (out_size >= B_ * MAXLEN + B_) {
        endp = xout + (out_size - B_);
    }

    permute_kernel<<<(TH3 * H_ + 255) / 256, 256>>>(in[4], in[5], in[8], in[9],
                                                    in[6], in[7], in[10], in[11], in[12]);
    init_state_kernel<<<(B_ + 255) / 256, 256>>>(xout, endp);
    gemm_init_k<<<dim3(H_ / 64, B_ / 64), 128>>>(z, lat_W, lat_b, 0);
    gemm_init_k<<<dim3(TH3 / 64, B_ / 64), 128>>>(z, nullptr, nullptr, 1);
    gemm_init_k<<<dim3(TH3 / 64, V_ / 64), 128>>>(in[1], nullptr, nullptr, 2);

    for (int s = 1; s < MAXLEN; s++) {
        int p = s & 1;
        step1_k<<<dim3(32, B_ / 64, 2), 64>>>(p);   // layer0 (z=0) + layer1 gh (z=1)
        gi_k<<<dim3(TH3 / 48, B_ / 64), 64>>>(p);   // layer1 gi
        fuse_k<<<B_ / 8, 256>>>(p, out_b, xout, endp, s);
    }
}